// round 10
// baseline (speedup 1.0000x reference)
#include <cuda_runtime.h>
#include <math.h>
#include <stdint.h>

#define Bc 4
#define Sc 2048
#define Ec 128
#define Hc 4
#define HDc 32
#define Mc (Bc*Sc)            // 8192 tokens
#define SSs ((size_t)Sc*(size_t)Sc)

// ---------------- scratch (device globals: allocation-free) ----------------
__device__ float g_X  [Mc*256];     // [M,256] relu(cat @ Win + b)
__device__ float g_q  [Mc*Ec];      // [B,H,S,HD]
__device__ float g_k  [Mc*Ec];      // [B,H,S,HD]
__device__ float g_v  [Mc*Ec];      // [B,H,S,HD]
__device__ float g_Zpp[16*Sc*32];   // per (bh,i,jt) tile-partial causal sums
__device__ float g_O  [Mc*Ec];      // [B,H,S,HD] attention output

// ---------------- tf32 helpers ----------------
__device__ __forceinline__ uint32_t f2tf(float x) {
    uint32_t r; asm("cvt.rna.tf32.f32 %0, %1;" : "=r"(r) : "f"(x)); return r;
}
__device__ __forceinline__ void mma_tf32(float (&d)[4], const uint32_t (&a)[4],
                                         const uint32_t (&b)[2]) {
    asm volatile("mma.sync.aligned.m16n8k8.row.col.f32.tf32.tf32.f32 "
        "{%0,%1,%2,%3}, {%4,%5,%6,%7}, {%8,%9}, {%0,%1,%2,%3};\n"
        : "+f"(d[0]), "+f"(d[1]), "+f"(d[2]), "+f"(d[3])
        : "r"(a[0]), "r"(a[1]), "r"(a[2]), "r"(a[3]), "r"(b[0]), "r"(b[1]));
}

// ---------------- tf32 MMA GEMM body with fused A-gather (pipelined) ----------------
// BM=128, BN=64, BK=32, 256 threads (8 warps: 4 along M x 2 along N, warp tile 32x32)
// MODE 0: plain A[M,KDIM]
// MODE 1: A = gated concat [itm*y, itm*(1-y), skl*y, skl*(1-y)]  (KDIM=512)
// MODE 2: A = [item_emb[ids], skill_emb[ids]]                     (KDIM=256)
template<int KDIM, int NDIM, int RELU, int HEADOUT, int MODE>
__device__ __forceinline__ void mm_body(const float* __restrict__ A, const float* __restrict__ W,
                                        const float* __restrict__ bias, float* __restrict__ out,
                                        int m0, int n0,
                                        const float* __restrict__ item_emb,
                                        const float* __restrict__ skill_emb,
                                        const int* __restrict__ idxA,
                                        const int* __restrict__ idxB,
                                        const int* __restrict__ lab)
{
    __shared__ uint32_t As[128][36];   // [m][k]
    __shared__ uint32_t Bs[32][72];    // [k][n]
    __shared__ int   sIA[128], sIB[128];
    __shared__ float sY[128];

    int tid = threadIdx.x;
    if (MODE != 0) {
        if (tid < 128) {
            int m = m0 + tid;
            sIA[tid] = idxA[m];
            sIB[tid] = idxB[m];
            if (MODE == 1) sY[tid] = (float)lab[m];
        }
        __syncthreads();
    }

    int w = tid >> 5, lane = tid & 31;
    int g = lane >> 2, tg = lane & 3;
    int wm = w & 3, wn = w >> 2;

    float acc[2][4][4];
    #pragma unroll
    for (int mi = 0; mi < 2; mi++)
        #pragma unroll
        for (int ni = 0; ni < 4; ni++)
            #pragma unroll
            for (int r = 0; r < 4; r++) acc[mi][ni][r] = 0.f;

    float4 av[4]; float4 wv[2];

    auto load_slab = [&](int kt) {
        #pragma unroll
        for (int t = 0; t < 4; t++) {
            int idx = tid + t*256;
            int r = idx >> 3, c = (idx & 7) * 4;
            if (MODE == 0) {
                av[t] = *(const float4*)&A[(size_t)(m0 + r)*KDIM + kt + c];
            } else {
                int k = kt + c;
                int seg = k >> 7, d = k & 127;
                const float* emb = (MODE == 1) ? ((seg < 2) ? item_emb : skill_emb)
                                               : (seg ? skill_emb : item_emb);
                int rowi = (MODE == 1) ? ((seg < 2) ? sIA[r] : sIB[r])
                                       : (seg ? sIB[r] : sIA[r]);
                float4 v = *(const float4*)&emb[(size_t)rowi*Ec + d];
                if (MODE == 1) {
                    float y = sY[r];
                    float gt = (seg & 1) ? (1.f - y) : y;
                    v.x *= gt; v.y *= gt; v.z *= gt; v.w *= gt;
                }
                av[t] = v;
            }
        }
        #pragma unroll
        for (int t = 0; t < 2; t++) {
            int idx = tid + t*256;
            int r = idx >> 4, c = (idx & 15) * 4;
            wv[t] = *(const float4*)&W[(size_t)(kt + r)*NDIM + n0 + c];
        }
    };

    load_slab(0);

    for (int kt = 0; kt < KDIM; kt += 32) {
        __syncthreads();
        #pragma unroll
        for (int t = 0; t < 4; t++) {
            int idx = tid + t*256;
            int r = idx >> 3, c = (idx & 7) * 4;
            uint4 u = { f2tf(av[t].x), f2tf(av[t].y), f2tf(av[t].z), f2tf(av[t].w) };
            *(uint4*)&As[r][c] = u;
        }
        #pragma unroll
        for (int t = 0; t < 2; t++) {
            int idx = tid + t*256;
            int r = idx >> 4, c = (idx & 15) * 4;
            uint4 u = { f2tf(wv[t].x), f2tf(wv[t].y), f2tf(wv[t].z), f2tf(wv[t].w) };
            *(uint4*)&Bs[r][c] = u;
        }
        __syncthreads();

        if (kt + 32 < KDIM) load_slab(kt + 32);   // prefetch hides behind mma below

        #pragma unroll
        for (int kk = 0; kk < 4; kk++) {
            uint32_t a[2][4], b[4][2];
            #pragma unroll
            for (int mi = 0; mi < 2; mi++) {
                int r = wm*32 + mi*16 + g;
                a[mi][0] = As[r][kk*8 + tg];
                a[mi][1] = As[r + 8][kk*8 + tg];
                a[mi][2] = As[r][kk*8 + tg + 4];
                a[mi][3] = As[r + 8][kk*8 + tg + 4];
            }
            #pragma unroll
            for (int ni = 0; ni < 4; ni++) {
                int c = wn*32 + ni*8 + g;
                b[ni][0] = Bs[kk*8 + tg][c];
                b[ni][1] = Bs[kk*8 + tg + 4][c];
            }
            #pragma unroll
            for (int mi = 0; mi < 2; mi++)
                #pragma unroll
                for (int ni = 0; ni < 4; ni++)
                    mma_tf32(acc[mi][ni], a[mi], b[ni]);
        }
    }

    #pragma unroll
    for (int mi = 0; mi < 2; mi++) {
        int rl = m0 + wm*32 + mi*16 + g;
        int rh = rl + 8;
        #pragma unroll
        for (int ni = 0; ni < 4; ni++) {
            int c = n0 + wn*32 + ni*8 + 2*tg;
            float b0 = bias[c], b1 = bias[c+1];
            float v00 = acc[mi][ni][0] + b0, v01 = acc[mi][ni][1] + b1;
            float v10 = acc[mi][ni][2] + b0, v11 = acc[mi][ni][3] + b1;
            if (RELU) {
                v00 = fmaxf(v00, 0.f); v01 = fmaxf(v01, 0.f);
                v10 = fmaxf(v10, 0.f); v11 = fmaxf(v11, 0.f);
            }
            float2 lo = {v00, v01}, hi = {v10, v11};
            if (!HEADOUT) {
                *(float2*)&out[(size_t)rl*NDIM + c] = lo;
                *(float2*)&out[(size_t)rh*NDIM + c] = hi;
            } else {
                int h = c >> 5, d = c & 31;
                *(float2*)&out[(((size_t)((rl >> 11)*Hc + h))*Sc + (rl & 2047))*HDc + d] = lo;
                *(float2*)&out[(((size_t)((rh >> 11)*Hc + h))*Sc + (rh & 2047))*HDc + d] = hi;
            }
        }
    }
}

// X = relu(cat @ Win + b), cat gathered on the fly. grid (4, 64)
__global__ __launch_bounds__(256) void win_kernel(const float* __restrict__ W,
                                                  const float* __restrict__ bias,
                                                  const float* __restrict__ item_emb,
                                                  const float* __restrict__ skill_emb,
                                                  const int* __restrict__ item_in,
                                                  const int* __restrict__ skill_in,
                                                  const int* __restrict__ label_in)
{
    mm_body<512, 256, 1, 0, 1>(nullptr, W, bias, g_X, blockIdx.y*128, blockIdx.x*64,
                               item_emb, skill_emb, item_in, skill_in, label_in);
}

// q/k/v in ONE launch: grid (6, 64); blockIdx.x>>1 selects q/k/v, &1 selects n-half
__global__ __launch_bounds__(256) void qkv_kernel(const float* __restrict__ Wq, const float* __restrict__ bq,
                                                  const float* __restrict__ Wk, const float* __restrict__ bk,
                                                  const float* __restrict__ Wv, const float* __restrict__ bv,
                                                  const float* __restrict__ item_emb,
                                                  const float* __restrict__ skill_emb,
                                                  const int* __restrict__ item_ids,
                                                  const int* __restrict__ skill_ids)
{
    int sel = blockIdx.x >> 1;
    int m0 = blockIdx.y*128, n0 = (blockIdx.x & 1)*64;
    if (sel == 0) {
        mm_body<256, 128, 0, 1, 2>(nullptr, Wq, bq, g_q, m0, n0,
                                   item_emb, skill_emb, item_ids, skill_ids, nullptr);
    } else if (sel == 1) {
        mm_body<256, 128, 0, 1, 0>(g_X, Wk, bk, g_k, m0, n0,
                                   nullptr, nullptr, nullptr, nullptr, nullptr);
    } else {
        mm_body<256, 128, 0, 1, 0>(g_X, Wv, bv, g_v, m0, n0,
                                   nullptr, nullptr, nullptr, nullptr, nullptr);
    }
}

// ---------------- balanced causal QK + deterministic tile row-sum partials ----------------
// grid (528 tile-pairs, 16 bh), 256 threads. Writes exp(q.k/sqrt(32)) raw.
__global__ __launch_bounds__(256) void qk_kernel(float* __restrict__ prob)
{
    __shared__ uint32_t Qs[64][36];
    __shared__ uint32_t Ks[64][36];
    __shared__ float red[64][4];
    int tid = threadIdx.x;
    int t = blockIdx.x, bh = blockIdx.y;

    // decode flattened lower-triangular (it, jt), jt <= it
    int it = (int)((sqrtf(8.f*(float)t + 1.f) - 1.f) * 0.5f);
    while ((it + 1)*(it + 2)/2 <= t) it++;
    while (it*(it + 1)/2 > t) it--;
    int jt = t - it*(it + 1)/2;

    int i0 = it * 64, j0 = jt * 64;
    const float* qp = g_q + (size_t)bh * Sc * HDc;
    const float* kp = g_k + (size_t)bh * Sc * HDc;

    int w = tid >> 5, lane = tid & 31;
    int g = lane >> 2, tg = lane & 3;
    int wm = w & 1, wn = w >> 1;        // warp tile 32(i) x 16(j)

    #pragma unroll
    for (int tt = 0; tt < 2; tt++) {
        int idx = tid + tt*256;
        int r = idx >> 3, c = (idx & 7) * 4;
        float4 v = *(const float4*)&qp[(size_t)(i0 + r)*HDc + c];
        uint4 u = { f2tf(v.x), f2tf(v.y), f2tf(v.z), f2tf(v.w) };
        *(uint4*)&Qs[r][c] = u;
        float4 kv = *(const float4*)&kp[(size_t)(j0 + r)*HDc + c];
        uint4 uk = { f2tf(kv.x), f2tf(kv.y), f2tf(kv.z), f2tf(kv.w) };
        *(uint4*)&Ks[r][c] = uk;
    }
    __syncthreads();

    float acc[2][2][4];
    #pragma unroll
    for (int mi = 0; mi < 2; mi++)
        #pragma unroll
        for (int ni = 0; ni < 2; ni++)
            #pragma unroll
            for (int r = 0; r < 4; r++) acc[mi][ni][r] = 0.f;

    #pragma unroll
    for (int kk = 0; kk < 4; kk++) {
        uint32_t a[2][4], b[2][2];
        #pragma unroll
        for (int mi = 0; mi < 2; mi++) {
            int r = wm*32 + mi*16 + g;
            a[mi][0] = Qs[r][kk*8 + tg];
            a[mi][1] = Qs[r + 8][kk*8 + tg];
            a[mi][2] = Qs[r][kk*8 + tg + 4];
            a[mi][3] = Qs[r + 8][kk*8 + tg + 4];
        }
        #pragma unroll
        for (int ni = 0; ni < 2; ni++) {
            int c = wn*16 + ni*8 + g;
            b[ni][0] = Ks[c][kk*8 + tg];
            b[ni][1] = Ks[c][kk*8 + tg + 4];
        }
        #pragma unroll
        for (int mi = 0; mi < 2; mi++)
            #pragma unroll
            for (int ni = 0; ni < 2; ni++)
                mma_tf32(acc[mi][ni], a[mi], b[ni]);
    }

    const float scale = 0.17677669529663687f;   // 1/sqrt(32)
    float* pbase = prob + (size_t)bh * SSs;
    float rs[2][2] = {{0.f,0.f},{0.f,0.f}};

    if (jt != it) {
        // off-diagonal: no masking (94% of blocks)
        #pragma unroll
        for (int mi = 0; mi < 2; mi++) {
            float* rowl = pbase + (size_t)(i0 + wm*32 + mi*16 + g) * Sc;
            float* rowh = rowl + (size_t)8 * Sc;
            #pragma unroll
            for (int ni = 0; ni < 2; ni++) {
                int cl = j0 + wn*16 + ni*8 + 2*tg;
                float e0 = __expf(acc[mi][ni][0]*scale);
                float e1 = __expf(acc[mi][ni][1]*scale);
                float e2 = __expf(acc[mi][ni][2]*scale);
                float e3 = __expf(acc[mi][ni][3]*scale);
                rs[mi][0] += e0 + e1;
                rs[mi][1] += e2 + e3;
                float2 lo = {e0, e1}, hi = {e2, e3};
                *(float2*)&rowl[cl] = lo;
                *(float2*)&rowh[cl] = hi;
            }
        }
    } else {
        // diagonal: causal mask
        #pragma unroll
        for (int mi = 0; mi < 2; mi++) {
            int rl = i0 + wm*32 + mi*16 + g;
            int rh = rl + 8;
            float* rowl = pbase + (size_t)rl * Sc;
            float* rowh = pbase + (size_t)rh * Sc;
            #pragma unroll
            for (int ni = 0; ni < 2; ni++) {
                int cl = j0 + wn*16 + ni*8 + 2*tg;
                float e0 = (cl     <= rl) ? __expf(acc[mi][ni][0]*scale) : 0.f;
                float e1 = (cl + 1 <= rl) ? __expf(acc[mi][ni][1]*scale) : 0.f;
                float e2 = (cl     <= rh) ? __expf(acc[mi][ni][2]*scale) : 0.f;
                float e3 = (cl + 1 <= rh) ? __expf(acc[mi][ni][3]*scale) : 0.f;
                rs[mi][0] += e0 + e1;
                rs[mi][1] += e2 + e3;
                float2 lo = {e0, e1}, hi = {e2, e3};
                *(float2*)&rowl[cl] = lo;
                *(float2*)&rowh[cl] = hi;
            }
        }
    }

    // deterministic tile row-sum partial -> g_Zpp[bh][i][jt]
    #pragma unroll
    for (int mi = 0; mi < 2; mi++)
        #pragma unroll
        for (int hf = 0; hf < 2; hf++) {
            float v = rs[mi][hf];
            v += __shfl_xor_sync(0xffffffffu, v, 1);
            v += __shfl_xor_sync(0xffffffffu, v, 2);
            if (tg == 0) red[wm*32 + mi*16 + g + hf*8][wn] = v;
        }
    __syncthreads();
    if (tid < 64) {
        float z = red[tid][0] + red[tid][1] + red[tid][2] + red[tid][3];
        g_Zpp[((size_t)bh*Sc + i0 + tid)*32 + jt] = z;
    }
}

// ---------------- combine (single-pass, low smem): blend + normalize ----------------
// One block per row (b, i). Zp from g_Zpp partials; E tile in 8KB smem;
// praw read exactly once. High occupancy.
__global__ __launch_bounds__(256) void combine_kernel(const float* __restrict__ rel,
        const float* __restrict__ ts, const float* __restrict__ l1p,
        const float* __restrict__ l2p, float* __restrict__ prob)
{
    __shared__ float E[Sc];          // exp of ts/rel (8KB)
    __shared__ float szt[8], szr[8];
    __shared__ float szp[4];
    int bi = blockIdx.x;             // row id = b*S + i
    int b = bi >> 11, i = bi & 2047;
    int tid = threadIdx.x;
    const float* tsr = ts  + (size_t)bi * Sc;
    const float* rlr = rel + (size_t)bi * Sc;
    size_t base0 = (size_t)(b*Hc)*SSs + (size_t)i*Sc;

    // Zp: warp h reduces the <=32 tile partials for head h
    if (tid < 128) {
        int h = tid >> 5, slot = tid & 31;
        int nt = (i >> 6) + 1;
        float v = (slot < nt) ? g_Zpp[((size_t)((b*Hc + h)*Sc) + i)*32 + slot] : 0.f;
        #pragma unroll
        for (int o = 16; o; o >>= 1) v += __shfl_xor_sync(0xffffffffu, v, o);
        if (slot == 0) szp[h] = v;
    }

    // phase 1: E tile + Zt/Zr reduction
    float zt = 0.f, zr = 0.f;
    #pragma unroll
    for (int t = 0; t < 2; t++) {
        int j = tid*4 + t*1024;
        if (j + 3 <= i) {
            float4 tv = *(const float4*)&tsr[j];
            float v0 = __expf(__expf(-fabsf(tv.x)));
            float v1 = __expf(__expf(-fabsf(tv.y)));
            float v2 = __expf(__expf(-fabsf(tv.z)));
            float v3 = __expf(__expf(-fabsf(tv.w)));
            *(float4*)&E[j] = make_float4(v0, v1, v2, v3);
            zt += (v0+v1) + (v2+v3);
        } else if (j > i) {
            float4 rv = *(const float4*)&rlr[j];
            float v0 = (rv.x == 0.f) ? 0.f : __expf(rv.x);
            float v1 = (rv.y == 0.f) ? 0.f : __expf(rv.y);
            float v2 = (rv.z == 0.f) ? 0.f : __expf(rv.z);
            float v3 = (rv.w == 0.f) ? 0.f : __expf(rv.w);
            *(float4*)&E[j] = make_float4(v0, v1, v2, v3);
            zr += (v0+v1) + (v2+v3);
        } else {
            #pragma unroll
            for (int u = 0; u < 4; u++) {
                int jj = j + u;
                if (jj <= i) {
                    float v = __expf(__expf(-fabsf(tsr[jj])));
                    E[jj] = v; zt += v;
                } else {
                    float rv = rlr[jj];
                    float v = (rv == 0.f) ? 0.f : __expf(rv);
                    E[jj] = v; zr += v;
                }
            }
        }
    }
    #pragma unroll
    for (int o = 16; o; o >>= 1) {
        zt += __shfl_xor_sync(0xffffffffu, zt, o);
        zr += __shfl_xor_sync(0xffffffffu, zr, o);
    }
    if ((tid & 31) == 0) { szt[tid >> 5] = zt; szr[tid >> 5] = zr; }
    __syncthreads();
    zt = 0.f; zr = 0.f;
    #pragma unroll
    for (int wi = 0; wi < 8; wi++) { zt += szt[wi]; zr += szr[wi]; }

    float l1 = *l1p, l2 = *l2p;
    float ct = (1.f - l1) * l2 / zt;
    float cr = 0.f, uni = 0.f;
    if (i == Sc - 1) uni = l1 / (float)Sc;   // all rel logits masked -> uniform softmax
    else             cr  = l1 / zr;
    float cp[4];
    #pragma unroll
    for (int h = 0; h < 4; h++)
        cp[h] = (1.f - l1) * (1.f - l2) / szp[h];

    // phase 2: read praw once, write final prob
    #pragma unroll
    for (int t = 0; t < 2; t++) {
        int j = tid*4 + t*1024;
        if (j + 3 <= i) {
            float4 e4 = *(float4*)&E[j];
            float a0 = ct*e4.x + uni, a1 = ct*e4.y + uni;
            float a2 = ct*e4.z + uni, a3 = ct*e4.w + uni;
            #pragma unroll
            for (int h = 0; h < 4; h++) {
                size_t a = base0 + (size_t)h*SSs + j;
                float4 p = *(const float4*)&prob[a];
                p.x = cp[h]*p.x + a0; p.y = cp[h]*p.y + a1;
                p.z = cp[h]*p.z + a2; p.w = cp[h]*p.w + a3;
                *(float4*)&prob[a] = p;
            }
        } else if (j > i) {
            float4 e4 = *(float4*)&E[j];
            float4 v = { cr*e4.x, cr*e4.y, cr*e4.z, cr*e4.w };
            #pragma unroll
            for (int h = 0; h < 4; h++)
                *(float4*)&prob[base0 + (size_t)h*SSs + j] = v;
        } else {
            #pragma unroll
            for (int u = 0; u < 4; u++) {
                int jj = j + u;
                if (jj <= i) {
                    float add = ct*E[jj] + uni;
                    #pragma unroll
                    for (int h = 0; h < 4; h++) {
                        size_t a = base0 + (size_t)h*SSs + jj;
                        prob[a] = cp[h]*prob[a] + add;
                    }
                } else {
                    float v = cr*E[jj];
                    #pragma unroll
                    for (int h = 0; h < 4; h++)
                        prob[base0 + (size_t)h*SSs + jj] = v;
                }
            }
        }
    }
}

// ---------------- AV (tf32 mma, pipelined): O = prob @ v ----------------
__global__ __launch_bounds__(256) void av_kernel(const float* __restrict__ prob)
{
    __shared__ uint32_t Ps[64][68];   // [i][k]
    __shared__ uint32_t Vs[64][36];   // [k][d]
    int tid = threadIdx.x;
    int it = blockIdx.x, bh = blockIdx.y;
    int i0 = it * 64;
    const float* pp = prob + (size_t)bh * SSs;
    const float* vp = g_v  + (size_t)bh * Sc * HDc;

    int w = tid >> 5, lane = tid & 31;
    int g = lane >> 2, tg = lane & 3;
    int wm = w & 3, wn = w >> 2;      // warp tile 16(i) x 16(d)

    int pr = tid >> 4, pc = (tid & 15) * 4;   // P-load coords
    int vr = tid >> 3, vc = (tid & 7) * 4;    // V-load coords

    float acc[2][4];
    #pragma unroll
    for (int ni = 0; ni < 2; ni++)
        #pragma unroll
        for (int r = 0; r < 4; r++) acc[ni][r] = 0.f;

    float4 pv[4]; float4 vv[2];
    #pragma unroll
    for (int t = 0; t < 4; t++)
        pv[t] = *(const float4*)&pp[(size_t)(i0 + pr + t*16)*Sc + pc];
    #pragma unroll
    for (int t = 0; t < 2; t++)
        vv[t] = *(const float4*)&vp[(size_t)(vr + t*32)*HDc + vc];

    for (int jt = 0; jt < Sc/64; jt++) {
        __syncthreads();
        #pragma unroll
        for (int t = 0; t < 4; t++) {
            uint4 u = { f2tf(pv[t].x), f2tf(pv[t].y), f2tf(pv[t].z), f2tf(pv[t].w) };
            *(uint4*)&Ps[pr + t*16][pc] = u;
        }
        #pragma unroll
        for (int t = 0; t < 2; t++) {
            uint4 u = { f2tf(vv[t].x), f2tf(vv[t].y), f2tf(vv[t].z), f2tf(vv[t].w) };
            *(uint4*)&Vs[vr + t*32][vc] = u;
        }
        __syncthreads();

        if (jt + 1 < Sc/64) {
            int j0n = (jt + 1) * 64;
            #pragma unroll
            for (int t = 0; t < 4; t++)
                pv[t] = *(const float4*)&pp[(size_t)(i0 + pr + t*16)*Sc + j0n + pc];
            #pragma unroll
            for (int t = 0; t < 2; t++)
                vv[t] = *(const float4*)&vp[(size_t)(j0n + vr + t*32)*HDc + vc];
        }

        #pragma unroll
        for (int kk = 0; kk < 8; kk++) {
            uint32_t a[4], b[2][2];
            int r = wm*16 + g;
            a[0] = Ps[r][kk*8 + tg];
            a[1] = Ps[r + 8][kk*8 + tg];
            a[2] = Ps[r][kk*8 + tg + 4];
            a[3] = Ps[r + 8][kk*8 + tg + 4];
            #pragma unroll
            for (int ni = 0; ni < 2; ni++) {
                int c = wn*16 + ni*8 + g;
                b[ni][0] = Vs[kk*8 + tg][c];
                b[ni][1] = Vs[kk*8 + tg + 4][c];
            }
            #pragma unroll
            for (int ni = 0; ni < 2; ni++)
                mma_tf32(acc[ni], a, b[ni]);
        }
    }

    int rl = i0 + wm*16 + g;
    int rh = rl + 8;
    #pragma unroll
    for (int ni = 0; ni < 2; ni++) {
        int c = wn*16 + ni*8 + 2*tg;
        float2 lo = {acc[ni][0], acc[ni][1]};
        float2 hi = {acc[ni][2], acc[ni][3]};
        *(float2*)&g_O[(size_t)(bh*Sc + rl)*HDc + c] = lo;
        *(float2*)&g_O[(size_t)(bh*Sc + rh)*HDc + c] = hi;
    }
}

// ---------------- pred = O @ Wout + bout ----------------
__global__ void pred_kernel(const float* __restrict__ Wout, const float* __restrict__ bout,
                            float* __restrict__ pred)
{
    __shared__ float sm[4];
    int m = blockIdx.x;
    int tid = threadIdx.x;           // 128 = e index (h*32+d)
    int b = m >> 11, s = m & 2047;
    int h = tid >> 5, d = tid & 31;
    float v = g_O[(((size_t)(b*Hc + h))*Sc + s)*HDc + d] * Wout[tid];
    #pragma unroll
    for (int o = 16; o; o >>= 1) v += __shfl_xor_sync(0xffffffffu, v, o);
    if ((tid & 31) == 0) sm[tid >> 5] = v;
    __syncthreads();
    if (tid == 0) pred[m] = sm[0] + sm[1] + sm[2] + sm[3] + bout[0];
}

// ---------------- launch ----------------
extern "C" void kernel_launch(void* const* d_in, const int* in_sizes, int n_in,
                              void* d_out, int out_size)
{
    (void)in_sizes; (void)n_in; (void)out_size;
    const int*   item_inputs  = (const int*)  d_in[0];
    const int*   skill_inputs = (const int*)  d_in[1];
    const int*   label_inputs = (const int*)  d_in[2];
    const int*   item_ids     = (const int*)  d_in[3];
    const int*   skill_ids    = (const int*)  d_in[4];
    const float* rel          = (const float*)d_in[5];
    const float* ts           = (const float*)d_in[6];
    const float* item_emb     = (const float*)d_in[7];
    const float* skill_emb    = (const float*)d_in[8];
    const float* Win          = (const float*)d_in[9];
    const float* b_in         = (const float*)d_in[10];
    const float* Wq           = (const float*)d_in[11];
    const float* bq           = (const float*)d_in[12];
    const float* Wk           = (const float*)d_in[13];
    const float* bk           = (const float*)d_in[14];
    const float* Wv           = (const float*)d_in[15];
    const float* bv           = (const float*)d_in[16];
    const float* Wout         = (const float*)d_in[17];
    const float* bout         = (const float*)d_in[18];
    const float* l1           = (const float*)d_in[19];
    const float* l2           = (const float*)d_in[20];

    float* pred = (float*)d_out;
    float* prob = pred + Mc;          // pred [8192] then prob_attn [B,H,S,S]

    win_kernel<<<dim3(4, 64), 256>>>(Win, b_in, item_emb, skill_emb,
                                     item_inputs, skill_inputs, label_inputs);
    qkv_kernel<<<dim3(6, 64), 256>>>(Wq, bq, Wk, bk, Wv, bv,
                                     item_emb, skill_emb, item_ids, skill_ids);
    qk_kernel<<<dim3(528, 16), 256>>>(prob);
    combine_kernel<<<Mc, 256>>>(rel, ts, l1, l2, prob);
    av_kernel<<<dim3(32, 16), 256>>>(prob);
    pred_kernel<<<Mc, 128>>>(Wout, bout, pred);
}

// round 11
// speedup vs baseline: 1.0154x; 1.0154x over previous
#include <cuda_runtime.h>
#include <math.h>
#include <stdint.h>

#define Bc 4
#define Sc 2048
#define Ec 128
#define Hc 4
#define HDc 32
#define Mc (Bc*Sc)            // 8192 tokens
#define SSs ((size_t)Sc*(size_t)Sc)

// ---------------- scratch (device globals: allocation-free) ----------------
__device__ float g_X  [Mc*256];   // [M,256] relu(cat @ Win + b)
__device__ float g_q  [Mc*Ec];    // [B,H,S,HD]
__device__ float g_k  [Mc*Ec];    // [B,H,S,HD]
__device__ float g_v  [Mc*Ec];    // [B,H,S,HD]
__device__ float g_O  [Mc*Ec];    // [B,H,S,HD] attention output

// ---------------- tf32 helpers ----------------
__device__ __forceinline__ uint32_t f2tf(float x) {
    uint32_t r; asm("cvt.rna.tf32.f32 %0, %1;" : "=r"(r) : "f"(x)); return r;
}
__device__ __forceinline__ void mma_tf32(float (&d)[4], const uint32_t (&a)[4],
                                         const uint32_t (&b)[2]) {
    asm volatile("mma.sync.aligned.m16n8k8.row.col.f32.tf32.tf32.f32 "
        "{%0,%1,%2,%3}, {%4,%5,%6,%7}, {%8,%9}, {%0,%1,%2,%3};\n"
        : "+f"(d[0]), "+f"(d[1]), "+f"(d[2]), "+f"(d[3])
        : "r"(a[0]), "r"(a[1]), "r"(a[2]), "r"(a[3]), "r"(b[0]), "r"(b[1]));
}

// ---------------- tf32 MMA GEMM body with fused A-gather (pipelined) ----------------
// BM=128, BN=64, BK=32, 256 threads (8 warps: 4 along M x 2 along N, warp tile 32x32)
// MODE 0: plain A[M,KDIM]
// MODE 1: A = gated concat [itm*y, itm*(1-y), skl*y, skl*(1-y)]  (KDIM=512)
// MODE 2: A = [item_emb[ids], skill_emb[ids]]                     (KDIM=256)
template<int KDIM, int NDIM, int RELU, int HEADOUT, int MODE>
__device__ __forceinline__ void mm_body(const float* __restrict__ A, const float* __restrict__ W,
                                        const float* __restrict__ bias, float* __restrict__ out,
                                        int m0, int n0,
                                        const float* __restrict__ item_emb,
                                        const float* __restrict__ skill_emb,
                                        const int* __restrict__ idxA,
                                        const int* __restrict__ idxB,
                                        const int* __restrict__ lab)
{
    __shared__ uint32_t As[128][36];   // [m][k]
    __shared__ uint32_t Bs[32][72];    // [k][n]
    __shared__ int   sIA[128], sIB[128];
    __shared__ float sY[128];

    int tid = threadIdx.x;
    if (MODE != 0) {
        if (tid < 128) {
            int m = m0 + tid;
            sIA[tid] = idxA[m];
            sIB[tid] = idxB[m];
            if (MODE == 1) sY[tid] = (float)lab[m];
        }
        __syncthreads();
    }

    int w = tid >> 5, lane = tid & 31;
    int g = lane >> 2, tg = lane & 3;
    int wm = w & 3, wn = w >> 2;

    float acc[2][4][4];
    #pragma unroll
    for (int mi = 0; mi < 2; mi++)
        #pragma unroll
        for (int ni = 0; ni < 4; ni++)
            #pragma unroll
            for (int r = 0; r < 4; r++) acc[mi][ni][r] = 0.f;

    float4 av[4]; float4 wv[2];

    auto load_slab = [&](int kt) {
        #pragma unroll
        for (int t = 0; t < 4; t++) {
            int idx = tid + t*256;
            int r = idx >> 3, c = (idx & 7) * 4;
            if (MODE == 0) {
                av[t] = *(const float4*)&A[(size_t)(m0 + r)*KDIM + kt + c];
            } else {
                int k = kt + c;
                int seg = k >> 7, d = k & 127;
                const float* emb = (MODE == 1) ? ((seg < 2) ? item_emb : skill_emb)
                                               : (seg ? skill_emb : item_emb);
                int rowi = (MODE == 1) ? ((seg < 2) ? sIA[r] : sIB[r])
                                       : (seg ? sIB[r] : sIA[r]);
                float4 v = *(const float4*)&emb[(size_t)rowi*Ec + d];
                if (MODE == 1) {
                    float y = sY[r];
                    float gt = (seg & 1) ? (1.f - y) : y;
                    v.x *= gt; v.y *= gt; v.z *= gt; v.w *= gt;
                }
                av[t] = v;
            }
        }
        #pragma unroll
        for (int t = 0; t < 2; t++) {
            int idx = tid + t*256;
            int r = idx >> 4, c = (idx & 15) * 4;
            wv[t] = *(const float4*)&W[(size_t)(kt + r)*NDIM + n0 + c];
        }
    };

    load_slab(0);

    for (int kt = 0; kt < KDIM; kt += 32) {
        __syncthreads();
        #pragma unroll
        for (int t = 0; t < 4; t++) {
            int idx = tid + t*256;
            int r = idx >> 3, c = (idx & 7) * 4;
            uint4 u = { f2tf(av[t].x), f2tf(av[t].y), f2tf(av[t].z), f2tf(av[t].w) };
            *(uint4*)&As[r][c] = u;
        }
        #pragma unroll
        for (int t = 0; t < 2; t++) {
            int idx = tid + t*256;
            int r = idx >> 4, c = (idx & 15) * 4;
            uint4 u = { f2tf(wv[t].x), f2tf(wv[t].y), f2tf(wv[t].z), f2tf(wv[t].w) };
            *(uint4*)&Bs[r][c] = u;
        }
        __syncthreads();

        if (kt + 32 < KDIM) load_slab(kt + 32);   // prefetch hides behind mma below

        #pragma unroll
        for (int kk = 0; kk < 4; kk++) {
            uint32_t a[2][4], b[4][2];
            #pragma unroll
            for (int mi = 0; mi < 2; mi++) {
                int r = wm*32 + mi*16 + g;
                a[mi][0] = As[r][kk*8 + tg];
                a[mi][1] = As[r + 8][kk*8 + tg];
                a[mi][2] = As[r][kk*8 + tg + 4];
                a[mi][3] = As[r + 8][kk*8 + tg + 4];
            }
            #pragma unroll
            for (int ni = 0; ni < 4; ni++) {
                int c = wn*32 + ni*8 + g;
                b[ni][0] = Bs[kk*8 + tg][c];
                b[ni][1] = Bs[kk*8 + tg + 4][c];
            }
            #pragma unroll
            for (int mi = 0; mi < 2; mi++)
                #pragma unroll
                for (int ni = 0; ni < 4; ni++)
                    mma_tf32(acc[mi][ni], a[mi], b[ni]);
        }
    }

    #pragma unroll
    for (int mi = 0; mi < 2; mi++) {
        int rl = m0 + wm*32 + mi*16 + g;
        int rh = rl + 8;
        #pragma unroll
        for (int ni = 0; ni < 4; ni++) {
            int c = n0 + wn*32 + ni*8 + 2*tg;
            float b0 = bias[c], b1 = bias[c+1];
            float v00 = acc[mi][ni][0] + b0, v01 = acc[mi][ni][1] + b1;
            float v10 = acc[mi][ni][2] + b0, v11 = acc[mi][ni][3] + b1;
            if (RELU) {
                v00 = fmaxf(v00, 0.f); v01 = fmaxf(v01, 0.f);
                v10 = fmaxf(v10, 0.f); v11 = fmaxf(v11, 0.f);
            }
            float2 lo = {v00, v01}, hi = {v10, v11};
            if (!HEADOUT) {
                *(float2*)&out[(size_t)rl*NDIM + c] = lo;
                *(float2*)&out[(size_t)rh*NDIM + c] = hi;
            } else {
                int h = c >> 5, d = c & 31;
                *(float2*)&out[(((size_t)((rl >> 11)*Hc + h))*Sc + (rl & 2047))*HDc + d] = lo;
                *(float2*)&out[(((size_t)((rh >> 11)*Hc + h))*Sc + (rh & 2047))*HDc + d] = hi;
            }
        }
    }
}

// X = relu(cat @ Win + b), cat gathered on the fly. grid (4, 64)
__global__ __launch_bounds__(256) void win_kernel(const float* __restrict__ W,
                                                  const float* __restrict__ bias,
                                                  const float* __restrict__ item_emb,
                                                  const float* __restrict__ skill_emb,
                                                  const int* __restrict__ item_in,
                                                  const int* __restrict__ skill_in,
                                                  const int* __restrict__ label_in)
{
    mm_body<512, 256, 1, 0, 1>(nullptr, W, bias, g_X, blockIdx.y*128, blockIdx.x*64,
                               item_emb, skill_emb, item_in, skill_in, label_in);
}

// q/k/v in ONE launch: grid (6, 64); blockIdx.x>>1 selects q/k/v, &1 selects n-half
__global__ __launch_bounds__(256) void qkv_kernel(const float* __restrict__ Wq, const float* __restrict__ bq,
                                                  const float* __restrict__ Wk, const float* __restrict__ bk,
                                                  const float* __restrict__ Wv, const float* __restrict__ bv,
                                                  const float* __restrict__ item_emb,
                                                  const float* __restrict__ skill_emb,
                                                  const int* __restrict__ item_ids,
                                                  const int* __restrict__ skill_ids)
{
    int sel = blockIdx.x >> 1;
    int m0 = blockIdx.y*128, n0 = (blockIdx.x & 1)*64;
    if (sel == 0) {
        mm_body<256, 128, 0, 1, 2>(nullptr, Wq, bq, g_q, m0, n0,
                                   item_emb, skill_emb, item_ids, skill_ids, nullptr);
    } else if (sel == 1) {
        mm_body<256, 128, 0, 1, 0>(g_X, Wk, bk, g_k, m0, n0,
                                   nullptr, nullptr, nullptr, nullptr, nullptr);
    } else {
        mm_body<256, 128, 0, 1, 0>(g_X, Wv, bv, g_v, m0, n0,
                                   nullptr, nullptr, nullptr, nullptr, nullptr);
    }
}

// ---------------- balanced causal QK: one 64x64 tile per block ----------------
// grid (528 tile-pairs, 16 bh), 256 threads. Writes exp(q.k/sqrt(32)) raw.
// Epilogue stages the exp tile in smem, then writes gmem with coalesced float4 rows.
__global__ __launch_bounds__(256) void qk_kernel(float* __restrict__ prob)
{
    __shared__ uint32_t Qs[64][36];
    __shared__ uint32_t Ks[64][36];
    __shared__ float Es[64][68];
    int tid = threadIdx.x;
    int t = blockIdx.x, bh = blockIdx.y;

    // decode flattened lower-triangular (it, jt), jt <= it
    int it = (int)((sqrtf(8.f*(float)t + 1.f) - 1.f) * 0.5f);
    while ((it + 1)*(it + 2)/2 <= t) it++;
    while (it*(it + 1)/2 > t) it--;
    int jt = t - it*(it + 1)/2;

    int i0 = it * 64, j0 = jt * 64;
    const float* qp = g_q + (size_t)bh * Sc * HDc;
    const float* kp = g_k + (size_t)bh * Sc * HDc;

    int w = tid >> 5, lane = tid & 31;
    int g = lane >> 2, tg = lane & 3;
    int wm = w & 1, wn = w >> 1;        // warp tile 32(i) x 16(j)

    // load Q (64x32) and K (64x32) tiles
    #pragma unroll
    for (int tt = 0; tt < 2; tt++) {
        int idx = tid + tt*256;
        int r = idx >> 3, c = (idx & 7) * 4;
        float4 v = *(const float4*)&qp[(size_t)(i0 + r)*HDc + c];
        uint4 u = { f2tf(v.x), f2tf(v.y), f2tf(v.z), f2tf(v.w) };
        *(uint4*)&Qs[r][c] = u;
        float4 kv = *(const float4*)&kp[(size_t)(j0 + r)*HDc + c];
        uint4 uk = { f2tf(kv.x), f2tf(kv.y), f2tf(kv.z), f2tf(kv.w) };
        *(uint4*)&Ks[r][c] = uk;
    }
    __syncthreads();

    float acc[2][2][4];
    #pragma unroll
    for (int mi = 0; mi < 2; mi++)
        #pragma unroll
        for (int ni = 0; ni < 2; ni++)
            #pragma unroll
            for (int r = 0; r < 4; r++) acc[mi][ni][r] = 0.f;

    #pragma unroll
    for (int kk = 0; kk < 4; kk++) {
        uint32_t a[2][4], b[2][2];
        #pragma unroll
        for (int mi = 0; mi < 2; mi++) {
            int r = wm*32 + mi*16 + g;
            a[mi][0] = Qs[r][kk*8 + tg];
            a[mi][1] = Qs[r + 8][kk*8 + tg];
            a[mi][2] = Qs[r][kk*8 + tg + 4];
            a[mi][3] = Qs[r + 8][kk*8 + tg + 4];
        }
        #pragma unroll
        for (int ni = 0; ni < 2; ni++) {
            int c = wn*16 + ni*8 + g;
            b[ni][0] = Ks[c][kk*8 + tg];
            b[ni][1] = Ks[c][kk*8 + tg + 4];
        }
        #pragma unroll
        for (int mi = 0; mi < 2; mi++)
            #pragma unroll
            for (int ni = 0; ni < 2; ni++)
                mma_tf32(acc[mi][ni], a[mi], b[ni]);
    }

    const float scale = 0.17677669529663687f;   // 1/sqrt(32)

    // stage exp tile in smem
    if (jt != it) {
        #pragma unroll
        for (int mi = 0; mi < 2; mi++) {
            int r = wm*32 + mi*16 + g;
            #pragma unroll
            for (int ni = 0; ni < 2; ni++) {
                int cl = wn*16 + ni*8 + 2*tg;
                float2 lo = { __expf(acc[mi][ni][0]*scale), __expf(acc[mi][ni][1]*scale) };
                float2 hi = { __expf(acc[mi][ni][2]*scale), __expf(acc[mi][ni][3]*scale) };
                *(float2*)&Es[r][cl] = lo;
                *(float2*)&Es[r + 8][cl] = hi;
            }
        }
    } else {
        #pragma unroll
        for (int mi = 0; mi < 2; mi++) {
            int r = wm*32 + mi*16 + g;
            int rl = i0 + r, rh = rl + 8;
            #pragma unroll
            for (int ni = 0; ni < 2; ni++) {
                int cl = wn*16 + ni*8 + 2*tg;
                int cg = j0 + cl;
                float e0 = (cg     <= rl) ? __expf(acc[mi][ni][0]*scale) : 0.f;
                float e1 = (cg + 1 <= rl) ? __expf(acc[mi][ni][1]*scale) : 0.f;
                float e2 = (cg     <= rh) ? __expf(acc[mi][ni][2]*scale) : 0.f;
                float e3 = (cg + 1 <= rh) ? __expf(acc[mi][ni][3]*scale) : 0.f;
                float2 lo = {e0, e1}, hi = {e2, e3};
                *(float2*)&Es[r][cl] = lo;
                *(float2*)&Es[r + 8][cl] = hi;
            }
        }
    }
    __syncthreads();

    // coalesced write: 16 threads x float4 = 256B contiguous per row
    float* pbase = prob + (size_t)bh * SSs;
    int sr = tid >> 4, sc = (tid & 15) * 4;
    #pragma unroll
    for (int tt = 0; tt < 4; tt++) {
        int row = sr + tt*16;
        float4 v = *(float4*)&Es[row][sc];
        *(float4*)&pbase[(size_t)(i0 + row)*Sc + j0 + sc] = v;
    }
}

// ---------------- combine: Zp reduction + time/rel softmax + blend + normalize ----------------
// One block per row (b, i). Stages raw causal prob in smem, reduces Zp per head,
// then rescales from smem. Bitwise deterministic.
__global__ __launch_bounds__(256) void combine_kernel(const float* __restrict__ rel,
        const float* __restrict__ ts, const float* __restrict__ l1p,
        const float* __restrict__ l2p, float* __restrict__ prob)
{
    __shared__ float Pr[4][Sc];      // raw causal prob rows (32KB)
    __shared__ float E[Sc];          // exp of ts/rel (8KB)
    __shared__ float sred[6][8];
    int bi = blockIdx.x;             // row id = b*S + i
    int b = bi >> 11, i = bi & 2047;
    int tid = threadIdx.x;
    const float* tsr = ts  + (size_t)bi * Sc;
    const float* rlr = rel + (size_t)bi * Sc;
    size_t base0 = (size_t)(b*Hc)*SSs + (size_t)i*Sc;

    float zt = 0.f, zr = 0.f;
    float zp[4] = {0.f, 0.f, 0.f, 0.f};

    #pragma unroll
    for (int t = 0; t < 2; t++) {
        int j = tid*4 + t*1024;
        if (j + 3 <= i) {
            float4 tv = *(const float4*)&tsr[j];
            float v0 = __expf(__expf(-fabsf(tv.x)));
            float v1 = __expf(__expf(-fabsf(tv.y)));
            float v2 = __expf(__expf(-fabsf(tv.z)));
            float v3 = __expf(__expf(-fabsf(tv.w)));
            *(float4*)&E[j] = make_float4(v0, v1, v2, v3);
            zt += (v0+v1) + (v2+v3);
            #pragma unroll
            for (int h = 0; h < 4; h++) {
                float4 p4 = *(const float4*)&prob[base0 + (size_t)h*SSs + j];
                *(float4*)&Pr[h][j] = p4;
                zp[h] += (p4.x + p4.y) + (p4.z + p4.w);
            }
        } else if (j > i) {
            float4 rv = *(const float4*)&rlr[j];
            float v0 = (rv.x == 0.f) ? 0.f : __expf(rv.x);
            float v1 = (rv.y == 0.f) ? 0.f : __expf(rv.y);
            float v2 = (rv.z == 0.f) ? 0.f : __expf(rv.z);
            float v3 = (rv.w == 0.f) ? 0.f : __expf(rv.w);
            *(float4*)&E[j] = make_float4(v0, v1, v2, v3);
            zr += (v0+v1) + (v2+v3);
        } else {
            #pragma unroll
            for (int u = 0; u < 4; u++) {
                int jj = j + u;
                if (jj <= i) {
                    float v = __expf(__expf(-fabsf(tsr[jj])));
                    E[jj] = v; zt += v;
                    #pragma unroll
                    for (int h = 0; h < 4; h++) {
                        float p = prob[base0 + (size_t)h*SSs + jj];
                        Pr[h][jj] = p; zp[h] += p;
                    }
                } else {
                    float rv = rlr[jj];
                    float v = (rv == 0.f) ? 0.f : __expf(rv);
                    E[jj] = v; zr += v;
                }
            }
        }
    }
    #pragma unroll
    for (int o = 16; o; o >>= 1) {
        zt += __shfl_xor_sync(0xffffffffu, zt, o);
        zr += __shfl_xor_sync(0xffffffffu, zr, o);
        #pragma unroll
        for (int h = 0; h < 4; h++) zp[h] += __shfl_xor_sync(0xffffffffu, zp[h], o);
    }
    if ((tid & 31) == 0) {
        int wi = tid >> 5;
        sred[0][wi] = zt; sred[1][wi] = zr;
        #pragma unroll
        for (int h = 0; h < 4; h++) sred[2 + h][wi] = zp[h];
    }
    __syncthreads();
    zt = 0.f; zr = 0.f; zp[0] = zp[1] = zp[2] = zp[3] = 0.f;
    #pragma unroll
    for (int wi = 0; wi < 8; wi++) {
        zt += sred[0][wi]; zr += sred[1][wi];
        #pragma unroll
        for (int h = 0; h < 4; h++) zp[h] += sred[2 + h][wi];
    }

    float l1 = *l1p, l2 = *l2p;
    float ct = (1.f - l1) * l2 / zt;
    float cr = 0.f, uni = 0.f;
    if (i == Sc - 1) uni = l1 / (float)Sc;   // all rel logits masked -> uniform softmax
    else             cr  = l1 / zr;
    float cp[4];
    #pragma unroll
    for (int h = 0; h < 4; h++)
        cp[h] = (1.f - l1) * (1.f - l2) / zp[h];

    #pragma unroll
    for (int t = 0; t < 2; t++) {
        int j = tid*4 + t*1024;
        if (j + 3 <= i) {
            float4 e4 = *(float4*)&E[j];
            float a0 = ct*e4.x + uni, a1 = ct*e4.y + uni;
            float a2 = ct*e4.z + uni, a3 = ct*e4.w + uni;
            #pragma unroll
            for (int h = 0; h < 4; h++) {
                float4 p = *(float4*)&Pr[h][j];
                p.x = cp[h]*p.x + a0; p.y = cp[h]*p.y + a1;
                p.z = cp[h]*p.z + a2; p.w = cp[h]*p.w + a3;
                *(float4*)&prob[base0 + (size_t)h*SSs + j] = p;
            }
        } else if (j > i) {
            float4 e4 = *(float4*)&E[j];
            float4 v = { cr*e4.x, cr*e4.y, cr*e4.z, cr*e4.w };
            #pragma unroll
            for (int h = 0; h < 4; h++)
                *(float4*)&prob[base0 + (size_t)h*SSs + j] = v;
        } else {
            #pragma unroll
            for (int u = 0; u < 4; u++) {
                int jj = j + u;
                if (jj <= i) {
                    float add = ct*E[jj] + uni;
                    #pragma unroll
                    for (int h = 0; h < 4; h++)
                        prob[base0 + (size_t)h*SSs + jj] = cp[h]*Pr[h][jj] + add;
                } else {
                    float v = cr*E[jj];
                    #pragma unroll
                    for (int h = 0; h < 4; h++)
                        prob[base0 + (size_t)h*SSs + jj] = v;
                }
            }
        }
    }
}

// ---------------- AV (tf32 mma, pipelined): O = prob @ v ----------------
__global__ __launch_bounds__(256) void av_kernel(const float* __restrict__ prob)
{
    __shared__ uint32_t Ps[64][68];   // [i][k]
    __shared__ uint32_t Vs[64][36];   // [k][d]
    int tid = threadIdx.x;
    int it = blockIdx.x, bh = blockIdx.y;
    int i0 = it * 64;
    const float* pp = prob + (size_t)bh * SSs;
    const float* vp = g_v  + (size_t)bh * Sc * HDc;

    int w = tid >> 5, lane = tid & 31;
    int g = lane >> 2, tg = lane & 3;
    int wm = w & 3, wn = w >> 2;      // warp tile 16(i) x 16(d)

    int pr = tid >> 4, pc = (tid & 15) * 4;   // P-load coords
    int vr = tid >> 3, vc = (tid & 7) * 4;    // V-load coords

    float acc[2][4];
    #pragma unroll
    for (int ni = 0; ni < 2; ni++)
        #pragma unroll
        for (int r = 0; r < 4; r++) acc[ni][r] = 0.f;

    float4 pv[4]; float4 vv[2];
    #pragma unroll
    for (int t = 0; t < 4; t++)
        pv[t] = *(const float4*)&pp[(size_t)(i0 + pr + t*16)*Sc + pc];
    #pragma unroll
    for (int t = 0; t < 2; t++)
        vv[t] = *(const float4*)&vp[(size_t)(vr + t*32)*HDc + vc];

    for (int jt = 0; jt < Sc/64; jt++) {
        __syncthreads();
        #pragma unroll
        for (int t = 0; t < 4; t++) {
            uint4 u = { f2tf(pv[t].x), f2tf(pv[t].y), f2tf(pv[t].z), f2tf(pv[t].w) };
            *(uint4*)&Ps[pr + t*16][pc] = u;
        }
        #pragma unroll
        for (int t = 0; t < 2; t++) {
            uint4 u = { f2tf(vv[t].x), f2tf(vv[t].y), f2tf(vv[t].z), f2tf(vv[t].w) };
            *(uint4*)&Vs[vr + t*32][vc] = u;
        }
        __syncthreads();

        if (jt + 1 < Sc/64) {
            int j0n = (jt + 1) * 64;
            #pragma unroll
            for (int t = 0; t < 4; t++)
                pv[t] = *(const float4*)&pp[(size_t)(i0 + pr + t*16)*Sc + j0n + pc];
            #pragma unroll
            for (int t = 0; t < 2; t++)
                vv[t] = *(const float4*)&vp[(size_t)(j0n + vr + t*32)*HDc + vc];
        }

        #pragma unroll
        for (int kk = 0; kk < 8; kk++) {
            uint32_t a[4], b[2][2];
            int r = wm*16 + g;
            a[0] = Ps[r][kk*8 + tg];
            a[1] = Ps[r + 8][kk*8 + tg];
            a[2] = Ps[r][kk*8 + tg + 4];
            a[3] = Ps[r + 8][kk*8 + tg + 4];
            #pragma unroll
            for (int ni = 0; ni < 2; ni++) {
                int c = wn*16 + ni*8 + g;
                b[ni][0] = Vs[kk*8 + tg][c];
                b[ni][1] = Vs[kk*8 + tg + 4][c];
            }
            #pragma unroll
            for (int ni = 0; ni < 2; ni++)
                mma_tf32(acc[ni], a, b[ni]);
        }
    }

    int rl = i0 + wm*16 + g;
    int rh = rl + 8;
    #pragma unroll
    for (int ni = 0; ni < 2; ni++) {
        int c = wn*16 + ni*8 + 2*tg;
        float2 lo = {acc[ni][0], acc[ni][1]};
        float2 hi = {acc[ni][2], acc[ni][3]};
        *(float2*)&g_O[(size_t)(bh*Sc + rl)*HDc + c] = lo;
        *(float2*)&g_O[(size_t)(bh*Sc + rh)*HDc + c] = hi;
    }
}

// ---------------- pred = O @ Wout + bout ----------------
__global__ void pred_kernel(const float* __restrict__ Wout, const float* __restrict__ bout,
                            float* __restrict__ pred)
{
    __shared__ float sm[4];
    int m = blockIdx.x;
    int tid = threadIdx.x;           // 128 = e index (h*32+d)
    int b = m >> 11, s = m & 2047;
    int h = tid >> 5, d = tid & 31;
    float v = g_O[(((size_t)(b*Hc + h))*Sc + s)*HDc + d] * Wout[tid];
    #pragma unroll
    for (int o = 16; o; o >>= 1) v += __shfl_xor_sync(0xffffffffu, v, o);
    if ((tid & 31) == 0) sm[tid >> 5] = v;
    __syncthreads();
    if (tid == 0) pred[m] = sm[0] + sm[1] + sm[2] + sm[3] + bout[0];
}

// ---------------- launch ----------------
extern "C" void kernel_launch(void* const* d_in, const int* in_sizes, int n_in,
                              void* d_out, int out_size)
{
    (void)in_sizes; (void)n_in; (void)out_size;
    const int*   item_inputs  = (const int*)  d_in[0];
    const int*   skill_inputs = (const int*)  d_in[1];
    const int*   label_inputs = (const int*)  d_in[2];
    const int*   item_ids     = (const int*)  d_in[3];
    const int*   skill_ids    = (const int*)  d_in[4];
    const float* rel          = (const float*)d_in[5];
    const float* ts           = (const float*)d_in[6];
    const float* item_emb     = (const float*)d_in[7];
    const float* skill_emb    = (const float*)d_in[8];
    const float* Win          = (const float*)d_in[9];
    const float* b_in         = (const float*)d_in[10];
    const float* Wq           = (const float*)d_in[11];
    const float* bq           = (const float*)d_in[12];
    const float* Wk           = (const float*)d_in[13];
    const float* bk           = (const float*)d_in[14];
    const float* Wv           = (const float*)d_in[15];
    const float* bv           = (const float*)d_in[16];
    const float* Wout         = (const float*)d_in[17];
    const float* bout         = (const float*)d_in[18];
    const float* l1           = (const float*)d_in[19];
    const float* l2           = (const float*)d_in[20];

    float* pred = (float*)d_out;
    float* prob = pred + Mc;          // pred [8192] then prob_attn [B,H,S,S]

    win_kernel<<<dim3(4, 64), 256>>>(Win, b_in, item_emb, skill_emb,
                                     item_inputs, skill_inputs, label_inputs);
    qkv_kernel<<<dim3(6, 64), 256>>>(Wq, bq, Wk, bk, Wv, bv,
                                     item_emb, skill_emb, item_ids, skill_ids);
    qk_kernel<<<dim3(528, 16), 256>>>(prob);
    combine_kernel<<<Mc, 256>>>(rel, ts, l1, l2, prob);
    av_kernel<<<dim3(32, 16), 256>>>(prob);
    pred_kernel<<<Mc, 128>>>(Wout, bout, pred);
}

// round 12
// speedup vs baseline: 1.4800x; 1.4576x over previous
#include <cuda_runtime.h>
#include <math.h>
#include <stdint.h>

#define Bc 4
#define Sc 2048
#define Ec 128
#define Hc 4
#define HDc 32
#define Mc (Bc*Sc)            // 8192 tokens
#define SSs ((size_t)Sc*(size_t)Sc)

// ---------------- scratch (device globals: allocation-free) ----------------
__device__ float g_X  [Mc*256];   // [M,256] relu(cat @ Win + b)
__device__ float g_q  [Mc*Ec];    // [B,H,S,HD]
__device__ float g_k  [Mc*Ec];    // [B,H,S,HD]
__device__ float g_v  [Mc*Ec];    // [B,H,S,HD]
__device__ float g_u  [16*Sc];    // u[bh,j] = v[bh,j,:] . Wout[h*32:h*32+32]

// ---------------- tf32 helpers ----------------
__device__ __forceinline__ uint32_t f2tf(float x) {
    uint32_t r; asm("cvt.rna.tf32.f32 %0, %1;" : "=r"(r) : "f"(x)); return r;
}
__device__ __forceinline__ void mma_tf32(float (&d)[4], const uint32_t (&a)[4],
                                         const uint32_t (&b)[2]) {
    asm volatile("mma.sync.aligned.m16n8k8.row.col.f32.tf32.tf32.f32 "
        "{%0,%1,%2,%3}, {%4,%5,%6,%7}, {%8,%9}, {%0,%1,%2,%3};\n"
        : "+f"(d[0]), "+f"(d[1]), "+f"(d[2]), "+f"(d[3])
        : "r"(a[0]), "r"(a[1]), "r"(a[2]), "r"(a[3]), "r"(b[0]), "r"(b[1]));
}

// ---------------- tf32 MMA GEMM body with fused A-gather (pipelined) ----------------
// BM=128, BN=64, BK=32, 256 threads (8 warps: 4 along M x 2 along N, warp tile 32x32)
// MODE 0: plain A[M,KDIM]
// MODE 1: A = gated concat [itm*y, itm*(1-y), skl*y, skl*(1-y)]  (KDIM=512)
// MODE 2: A = [item_emb[ids], skill_emb[ids]]                     (KDIM=256)
template<int KDIM, int NDIM, int RELU, int HEADOUT, int MODE>
__device__ __forceinline__ void mm_body(const float* __restrict__ A, const float* __restrict__ W,
                                        const float* __restrict__ bias, float* __restrict__ out,
                                        int m0, int n0,
                                        const float* __restrict__ item_emb,
                                        const float* __restrict__ skill_emb,
                                        const int* __restrict__ idxA,
                                        const int* __restrict__ idxB,
                                        const int* __restrict__ lab)
{
    __shared__ uint32_t As[128][36];   // [m][k]
    __shared__ uint32_t Bs[32][72];    // [k][n]
    __shared__ int   sIA[128], sIB[128];
    __shared__ float sY[128];

    int tid = threadIdx.x;
    if (MODE != 0) {
        if (tid < 128) {
            int m = m0 + tid;
            sIA[tid] = idxA[m];
            sIB[tid] = idxB[m];
            if (MODE == 1) sY[tid] = (float)lab[m];
        }
        __syncthreads();
    }

    int w = tid >> 5, lane = tid & 31;
    int g = lane >> 2, tg = lane & 3;
    int wm = w & 3, wn = w >> 2;

    float acc[2][4][4];
    #pragma unroll
    for (int mi = 0; mi < 2; mi++)
        #pragma unroll
        for (int ni = 0; ni < 4; ni++)
            #pragma unroll
            for (int r = 0; r < 4; r++) acc[mi][ni][r] = 0.f;

    float4 av[4]; float4 wv[2];

    auto load_slab = [&](int kt) {
        #pragma unroll
        for (int t = 0; t < 4; t++) {
            int idx = tid + t*256;
            int r = idx >> 3, c = (idx & 7) * 4;
            if (MODE == 0) {
                av[t] = *(const float4*)&A[(size_t)(m0 + r)*KDIM + kt + c];
            } else {
                int k = kt + c;
                int seg = k >> 7, d = k & 127;
                const float* emb = (MODE == 1) ? ((seg < 2) ? item_emb : skill_emb)
                                               : (seg ? skill_emb : item_emb);
                int rowi = (MODE == 1) ? ((seg < 2) ? sIA[r] : sIB[r])
                                       : (seg ? sIB[r] : sIA[r]);
                float4 v = *(const float4*)&emb[(size_t)rowi*Ec + d];
                if (MODE == 1) {
                    float y = sY[r];
                    float gt = (seg & 1) ? (1.f - y) : y;
                    v.x *= gt; v.y *= gt; v.z *= gt; v.w *= gt;
                }
                av[t] = v;
            }
        }
        #pragma unroll
        for (int t = 0; t < 2; t++) {
            int idx = tid + t*256;
            int r = idx >> 4, c = (idx & 15) * 4;
            wv[t] = *(const float4*)&W[(size_t)(kt + r)*NDIM + n0 + c];
        }
    };

    load_slab(0);

    for (int kt = 0; kt < KDIM; kt += 32) {
        __syncthreads();
        #pragma unroll
        for (int t = 0; t < 4; t++) {
            int idx = tid + t*256;
            int r = idx >> 3, c = (idx & 7) * 4;
            uint4 u = { f2tf(av[t].x), f2tf(av[t].y), f2tf(av[t].z), f2tf(av[t].w) };
            *(uint4*)&As[r][c] = u;
        }
        #pragma unroll
        for (int t = 0; t < 2; t++) {
            int idx = tid + t*256;
            int r = idx >> 4, c = (idx & 15) * 4;
            uint4 u = { f2tf(wv[t].x), f2tf(wv[t].y), f2tf(wv[t].z), f2tf(wv[t].w) };
            *(uint4*)&Bs[r][c] = u;
        }
        __syncthreads();

        if (kt + 32 < KDIM) load_slab(kt + 32);   // prefetch hides behind mma below

        #pragma unroll
        for (int kk = 0; kk < 4; kk++) {
            uint32_t a[2][4], b[4][2];
            #pragma unroll
            for (int mi = 0; mi < 2; mi++) {
                int r = wm*32 + mi*16 + g;
                a[mi][0] = As[r][kk*8 + tg];
                a[mi][1] = As[r + 8][kk*8 + tg];
                a[mi][2] = As[r][kk*8 + tg + 4];
                a[mi][3] = As[r + 8][kk*8 + tg + 4];
            }
            #pragma unroll
            for (int ni = 0; ni < 4; ni++) {
                int c = wn*32 + ni*8 + g;
                b[ni][0] = Bs[kk*8 + tg][c];
                b[ni][1] = Bs[kk*8 + tg + 4][c];
            }
            #pragma unroll
            for (int mi = 0; mi < 2; mi++)
                #pragma unroll
                for (int ni = 0; ni < 4; ni++)
                    mma_tf32(acc[mi][ni], a[mi], b[ni]);
        }
    }

    #pragma unroll
    for (int mi = 0; mi < 2; mi++) {
        int rl = m0 + wm*32 + mi*16 + g;
        int rh = rl + 8;
        #pragma unroll
        for (int ni = 0; ni < 4; ni++) {
            int c = n0 + wn*32 + ni*8 + 2*tg;
            float b0 = bias[c], b1 = bias[c+1];
            float v00 = acc[mi][ni][0] + b0, v01 = acc[mi][ni][1] + b1;
            float v10 = acc[mi][ni][2] + b0, v11 = acc[mi][ni][3] + b1;
            if (RELU) {
                v00 = fmaxf(v00, 0.f); v01 = fmaxf(v01, 0.f);
                v10 = fmaxf(v10, 0.f); v11 = fmaxf(v11, 0.f);
            }
            float2 lo = {v00, v01}, hi = {v10, v11};
            if (!HEADOUT) {
                *(float2*)&out[(size_t)rl*NDIM + c] = lo;
                *(float2*)&out[(size_t)rh*NDIM + c] = hi;
            } else {
                int h = c >> 5, d = c & 31;
                *(float2*)&out[(((size_t)((rl >> 11)*Hc + h))*Sc + (rl & 2047))*HDc + d] = lo;
                *(float2*)&out[(((size_t)((rh >> 11)*Hc + h))*Sc + (rh & 2047))*HDc + d] = hi;
            }
        }
    }
}

// X = relu(cat @ Win + b), cat gathered on the fly. grid (4, 64)
__global__ __launch_bounds__(256) void win_kernel(const float* __restrict__ W,
                                                  const float* __restrict__ bias,
                                                  const float* __restrict__ item_emb,
                                                  const float* __restrict__ skill_emb,
                                                  const int* __restrict__ item_in,
                                                  const int* __restrict__ skill_in,
                                                  const int* __restrict__ label_in)
{
    mm_body<512, 256, 1, 0, 1>(nullptr, W, bias, g_X, blockIdx.y*128, blockIdx.x*64,
                               item_emb, skill_emb, item_in, skill_in, label_in);
}

// q/k/v in ONE launch: grid (6, 64); blockIdx.x>>1 selects q/k/v, &1 selects n-half
__global__ __launch_bounds__(256) void qkv_kernel(const float* __restrict__ Wq, const float* __restrict__ bq,
                                                  const float* __restrict__ Wk, const float* __restrict__ bk,
                                                  const float* __restrict__ Wv, const float* __restrict__ bv,
                                                  const float* __restrict__ item_emb,
                                                  const float* __restrict__ skill_emb,
                                                  const int* __restrict__ item_ids,
                                                  const int* __restrict__ skill_ids)
{
    int sel = blockIdx.x >> 1;
    int m0 = blockIdx.y*128, n0 = (blockIdx.x & 1)*64;
    if (sel == 0) {
        mm_body<256, 128, 0, 1, 2>(nullptr, Wq, bq, g_q, m0, n0,
                                   item_emb, skill_emb, item_ids, skill_ids, nullptr);
    } else if (sel == 1) {
        mm_body<256, 128, 0, 1, 0>(g_X, Wk, bk, g_k, m0, n0,
                                   nullptr, nullptr, nullptr, nullptr, nullptr);
    } else {
        mm_body<256, 128, 0, 1, 0>(g_X, Wv, bv, g_v, m0, n0,
                                   nullptr, nullptr, nullptr, nullptr, nullptr);
    }
}

// ---------------- u[bh,j] = v[bh,j,:] . Wout[h*32 : h*32+32] ----------------
__global__ void u_kernel(const float* __restrict__ Wout)
{
    int idx = blockIdx.x*256 + threadIdx.x;   // 0..32767 = bh*Sc + j
    int h = (idx >> 11) & 3;
    const float* vr = g_v + (size_t)idx * HDc;
    const float* wo = Wout + h*32;
    float s = 0.f;
    #pragma unroll
    for (int d4 = 0; d4 < 8; d4++) {
        float4 v4 = *(const float4*)&vr[d4*4];
        float4 w4 = *(const float4*)&wo[d4*4];
        s += v4.x*w4.x + v4.y*w4.y + v4.z*w4.z + v4.w*w4.w;
    }
    g_u[idx] = s;
}

// ---------------- balanced causal QK: one 64x64 tile per block ----------------
// grid (528 tile-pairs, 16 bh), 256 threads. Writes exp(q.k/sqrt(32)) raw; no row sums.
__global__ __launch_bounds__(256) void qk_kernel(float* __restrict__ prob)
{
    __shared__ uint32_t Qs[64][36];
    __shared__ uint32_t Ks[64][36];
    int tid = threadIdx.x;
    int t = blockIdx.x, bh = blockIdx.y;

    // decode flattened lower-triangular (it, jt), jt <= it
    int it = (int)((sqrtf(8.f*(float)t + 1.f) - 1.f) * 0.5f);
    while ((it + 1)*(it + 2)/2 <= t) it++;
    while (it*(it + 1)/2 > t) it--;
    int jt = t - it*(it + 1)/2;

    int i0 = it * 64, j0 = jt * 64;
    const float* qp = g_q + (size_t)bh * Sc * HDc;
    const float* kp = g_k + (size_t)bh * Sc * HDc;

    int w = tid >> 5, lane = tid & 31;
    int g = lane >> 2, tg = lane & 3;
    int wm = w & 1, wn = w >> 1;        // warp tile 32(i) x 16(j)

    // load Q (64x32) and K (64x32) tiles
    #pragma unroll
    for (int tt = 0; tt < 2; tt++) {
        int idx = tid + tt*256;
        int r = idx >> 3, c = (idx & 7) * 4;
        float4 v = *(const float4*)&qp[(size_t)(i0 + r)*HDc + c];
        uint4 u = { f2tf(v.x), f2tf(v.y), f2tf(v.z), f2tf(v.w) };
        *(uint4*)&Qs[r][c] = u;
        float4 kv = *(const float4*)&kp[(size_t)(j0 + r)*HDc + c];
        uint4 uk = { f2tf(kv.x), f2tf(kv.y), f2tf(kv.z), f2tf(kv.w) };
        *(uint4*)&Ks[r][c] = uk;
    }
    __syncthreads();

    float acc[2][2][4];
    #pragma unroll
    for (int mi = 0; mi < 2; mi++)
        #pragma unroll
        for (int ni = 0; ni < 2; ni++)
            #pragma unroll
            for (int r = 0; r < 4; r++) acc[mi][ni][r] = 0.f;

    #pragma unroll
    for (int kk = 0; kk < 4; kk++) {
        uint32_t a[2][4], b[2][2];
        #pragma unroll
        for (int mi = 0; mi < 2; mi++) {
            int r = wm*32 + mi*16 + g;
            a[mi][0] = Qs[r][kk*8 + tg];
            a[mi][1] = Qs[r + 8][kk*8 + tg];
            a[mi][2] = Qs[r][kk*8 + tg + 4];
            a[mi][3] = Qs[r + 8][kk*8 + tg + 4];
        }
        #pragma unroll
        for (int ni = 0; ni < 2; ni++) {
            int c = wn*16 + ni*8 + g;
            b[ni][0] = Ks[c][kk*8 + tg];
            b[ni][1] = Ks[c][kk*8 + tg + 4];
        }
        #pragma unroll
        for (int mi = 0; mi < 2; mi++)
            #pragma unroll
            for (int ni = 0; ni < 2; ni++)
                mma_tf32(acc[mi][ni], a[mi], b[ni]);
    }

    const float scale = 0.17677669529663687f;   // 1/sqrt(32)
    float* pbase = prob + (size_t)bh * SSs;

    if (jt != it) {
        // off-diagonal: no masking at all (94% of blocks)
        #pragma unroll
        for (int mi = 0; mi < 2; mi++) {
            float* rowl = pbase + (size_t)(i0 + wm*32 + mi*16 + g) * Sc;
            float* rowh = rowl + (size_t)8 * Sc;
            #pragma unroll
            for (int ni = 0; ni < 2; ni++) {
                int cl = j0 + wn*16 + ni*8 + 2*tg;
                float2 lo = { __expf(acc[mi][ni][0]*scale), __expf(acc[mi][ni][1]*scale) };
                float2 hi = { __expf(acc[mi][ni][2]*scale), __expf(acc[mi][ni][3]*scale) };
                *(float2*)&rowl[cl] = lo;
                *(float2*)&rowh[cl] = hi;
            }
        }
    } else {
        // diagonal: causal mask
        #pragma unroll
        for (int mi = 0; mi < 2; mi++) {
            int rl = i0 + wm*32 + mi*16 + g;
            int rh = rl + 8;
            float* rowl = pbase + (size_t)rl * Sc;
            float* rowh = pbase + (size_t)rh * Sc;
            #pragma unroll
            for (int ni = 0; ni < 2; ni++) {
                int cl = j0 + wn*16 + ni*8 + 2*tg;
                float e0 = (cl     <= rl) ? __expf(acc[mi][ni][0]*scale) : 0.f;
                float e1 = (cl + 1 <= rl) ? __expf(acc[mi][ni][1]*scale) : 0.f;
                float e2 = (cl     <= rh) ? __expf(acc[mi][ni][2]*scale) : 0.f;
                float e3 = (cl + 1 <= rh) ? __expf(acc[mi][ni][3]*scale) : 0.f;
                float2 lo = {e0, e1}, hi = {e2, e3};
                *(float2*)&rowl[cl] = lo;
                *(float2*)&rowh[cl] = hi;
            }
        }
    }
}

// ---------------- combine: Zp reduction + softmax blend + normalize + PRED ----------------
// One block per row (b, i). Stages raw causal prob in smem, reduces Zp per head,
// rescales from smem, accumulates pred[b,i] = sum_h sum_j prob*u + bout on the fly.
__global__ __launch_bounds__(256) void combine_kernel(const float* __restrict__ rel,
        const float* __restrict__ ts, const float* __restrict__ l1p,
        const float* __restrict__ l2p, const float* __restrict__ bout,
        float* __restrict__ prob, float* __restrict__ pred)
{
    __shared__ float Pr[4][Sc];      // raw causal prob rows (32KB)
    __shared__ float E[Sc];          // exp of ts/rel (8KB)
    __shared__ float sred[6][8];
    __shared__ float spred[8];
    int bi = blockIdx.x;             // row id = b*S + i
    int b = bi >> 11, i = bi & 2047;
    int tid = threadIdx.x;
    const float* tsr = ts  + (size_t)bi * Sc;
    const float* rlr = rel + (size_t)bi * Sc;
    size_t base0 = (size_t)(b*Hc)*SSs + (size_t)i*Sc;

    float zt = 0.f, zr = 0.f;
    float zp[4] = {0.f, 0.f, 0.f, 0.f};

    #pragma unroll
    for (int t = 0; t < 2; t++) {
        int j = tid*4 + t*1024;
        if (j + 3 <= i) {
            float4 tv = *(const float4*)&tsr[j];
            float v0 = __expf(__expf(-fabsf(tv.x)));
            float v1 = __expf(__expf(-fabsf(tv.y)));
            float v2 = __expf(__expf(-fabsf(tv.z)));
            float v3 = __expf(__expf(-fabsf(tv.w)));
            *(float4*)&E[j] = make_float4(v0, v1, v2, v3);
            zt += (v0+v1) + (v2+v3);
            #pragma unroll
            for (int h = 0; h < 4; h++) {
                float4 p4 = *(const float4*)&prob[base0 + (size_t)h*SSs + j];
                *(float4*)&Pr[h][j] = p4;
                zp[h] += (p4.x + p4.y) + (p4.z + p4.w);
            }
        } else if (j > i) {
            float4 rv = *(const float4*)&rlr[j];
            float v0 = (rv.x == 0.f) ? 0.f : __expf(rv.x);
            float v1 = (rv.y == 0.f) ? 0.f : __expf(rv.y);
            float v2 = (rv.z == 0.f) ? 0.f : __expf(rv.z);
            float v3 = (rv.w == 0.f) ? 0.f : __expf(rv.w);
            *(float4*)&E[j] = make_float4(v0, v1, v2, v3);
            zr += (v0+v1) + (v2+v3);
        } else {
            #pragma unroll
            for (int u = 0; u < 4; u++) {
                int jj = j + u;
                if (jj <= i) {
                    float v = __expf(__expf(-fabsf(tsr[jj])));
                    E[jj] = v; zt += v;
                    #pragma unroll
                    for (int h = 0; h < 4; h++) {
                        float p = prob[base0 + (size_t)h*SSs + jj];
                        Pr[h][jj] = p; zp[h] += p;
                    }
                } else {
                    float rv = rlr[jj];
                    float v = (rv == 0.f) ? 0.f : __expf(rv);
                    E[jj] = v; zr += v;
                }
            }
        }
    }
    #pragma unroll
    for (int o = 16; o; o >>= 1) {
        zt += __shfl_xor_sync(0xffffffffu, zt, o);
        zr += __shfl_xor_sync(0xffffffffu, zr, o);
        #pragma unroll
        for (int h = 0; h < 4; h++) zp[h] += __shfl_xor_sync(0xffffffffu, zp[h], o);
    }
    if ((tid & 31) == 0) {
        int wi = tid >> 5;
        sred[0][wi] = zt; sred[1][wi] = zr;
        #pragma unroll
        for (int h = 0; h < 4; h++) sred[2 + h][wi] = zp[h];
    }
    __syncthreads();
    zt = 0.f; zr = 0.f; zp[0] = zp[1] = zp[2] = zp[3] = 0.f;
    #pragma unroll
    for (int wi = 0; wi < 8; wi++) {
        zt += sred[0][wi]; zr += sred[1][wi];
        #pragma unroll
        for (int h = 0; h < 4; h++) zp[h] += sred[2 + h][wi];
    }

    float l1 = *l1p, l2 = *l2p;
    float ct = (1.f - l1) * l2 / zt;
    float cr = 0.f, uni = 0.f;
    if (i == Sc - 1) uni = l1 / (float)Sc;   // all rel logits masked -> uniform softmax
    else             cr  = l1 / zr;
    float cp[4];
    #pragma unroll
    for (int h = 0; h < 4; h++)
        cp[h] = (1.f - l1) * (1.f - l2) / zp[h];

    float pacc = 0.f;
    #pragma unroll
    for (int t = 0; t < 2; t++) {
        int j = tid*4 + t*1024;
        float4 u4[4];
        #pragma unroll
        for (int h = 0; h < 4; h++)
            u4[h] = *(const float4*)&g_u[(size_t)((b*Hc + h)*Sc) + j];
        if (j + 3 <= i) {
            float4 e4 = *(float4*)&E[j];
            float a0 = ct*e4.x + uni, a1 = ct*e4.y + uni;
            float a2 = ct*e4.z + uni, a3 = ct*e4.w + uni;
            #pragma unroll
            for (int h = 0; h < 4; h++) {
                float4 p = *(float4*)&Pr[h][j];
                p.x = cp[h]*p.x + a0; p.y = cp[h]*p.y + a1;
                p.z = cp[h]*p.z + a2; p.w = cp[h]*p.w + a3;
                *(float4*)&prob[base0 + (size_t)h*SSs + j] = p;
                pacc += p.x*u4[h].x + p.y*u4[h].y + p.z*u4[h].z + p.w*u4[h].w;
            }
        } else if (j > i) {
            float4 e4 = *(float4*)&E[j];
            float4 v = { cr*e4.x, cr*e4.y, cr*e4.z, cr*e4.w };
            float4 us = { u4[0].x + u4[1].x + u4[2].x + u4[3].x,
                          u4[0].y + u4[1].y + u4[2].y + u4[3].y,
                          u4[0].z + u4[1].z + u4[2].z + u4[3].z,
                          u4[0].w + u4[1].w + u4[2].w + u4[3].w };
            #pragma unroll
            for (int h = 0; h < 4; h++)
                *(float4*)&prob[base0 + (size_t)h*SSs + j] = v;
            pacc += v.x*us.x + v.y*us.y + v.z*us.z + v.w*us.w;
        } else {
            #pragma unroll
            for (int u = 0; u < 4; u++) {
                int jj = j + u;
                float uu[4] = { ((float*)&u4[0])[u], ((float*)&u4[1])[u],
                                ((float*)&u4[2])[u], ((float*)&u4[3])[u] };
                if (jj <= i) {
                    float add = ct*E[jj] + uni;
                    #pragma unroll
                    for (int h = 0; h < 4; h++) {
                        float p = cp[h]*Pr[h][jj] + add;
                        prob[base0 + (size_t)h*SSs + jj] = p;
                        pacc += p * uu[h];
                    }
                } else {
                    float v = cr*E[jj];
                    #pragma unroll
                    for (int h = 0; h < 4; h++) {
                        prob[base0 + (size_t)h*SSs + jj] = v;
                        pacc += v * uu[h];
                    }
                }
            }
        }
    }

    // reduce pred across block
    #pragma unroll
    for (int o = 16; o; o >>= 1) pacc += __shfl_xor_sync(0xffffffffu, pacc, o);
    if ((tid & 31) == 0) spred[tid >> 5] = pacc;
    __syncthreads();
    if (tid == 0) {
        float s = 0.f;
        #pragma unroll
        for (int wi = 0; wi < 8; wi++) s += spred[wi];
        pred[bi] = s + bout[0];
    }
}

// ---------------- launch ----------------
extern "C" void kernel_launch(void* const* d_in, const int* in_sizes, int n_in,
                              void* d_out, int out_size)
{
    (void)in_sizes; (void)n_in; (void)out_size;
    const int*   item_inputs  = (const int*)  d_in[0];
    const int*   skill_inputs = (const int*)  d_in[1];
    const int*   label_inputs = (const int*)  d_in[2];
    const int*   item_ids     = (const int*)  d_in[3];
    const int*   skill_ids    = (const int*)  d_in[4];
    const float* rel          = (const float*)d_in[5];
    const float* ts           = (const float*)d_in[6];
    const float* item_emb     = (const float*)d_in[7];
    const float* skill_emb    = (const float*)d_in[8];
    const float* Win          = (const float*)d_in[9];
    const float* b_in         = (const float*)d_in[10];
    const float* Wq           = (const float*)d_in[11];
    const float* bq           = (const float*)d_in[12];
    const float* Wk           = (const float*)d_in[13];
    const float* bk           = (const float*)d_in[14];
    const float* Wv           = (const float*)d_in[15];
    const float* bv           = (const float*)d_in[16];
    const float* Wout         = (const float*)d_in[17];
    const float* bout         = (const float*)d_in[18];
    const float* l1           = (const float*)d_in[19];
    const float* l2           = (const float*)d_in[20];

    float* pred = (float*)d_out;
    float* prob = pred + Mc;          // pred [8192] then prob_attn [B,H,S,S]

    win_kernel<<<dim3(4, 64), 256>>>(Win, b_in, item_emb, skill_emb,
                                     item_inputs, skill_inputs, label_inputs);
    qkv_kernel<<<dim3(6, 64), 256>>>(Wq, bq, Wk, bk, Wv, bv,
                                     item_emb, skill_emb, item_ids, skill_ids);
    u_kernel<<<128, 256>>>(Wout);
    qk_kernel<<<dim3(528, 16), 256>>>(prob);
    combine_kernel<<<Mc, 256>>>(rel, ts, l1, l2, bout, prob, pred);
}

// round 13
// speedup vs baseline: 1.5943x; 1.0772x over previous
#include <cuda_runtime.h>
#include <cuda_bf16.h>
#include <math.h>
#include <stdint.h>

#define Bc 4
#define Sc 2048
#define Ec 128
#define Hc 4
#define HDc 32
#define Mc (Bc*Sc)            // 8192 tokens
#define SSs ((size_t)Sc*(size_t)Sc)

// ---------------- scratch (device globals: allocation-free) ----------------
__device__ float g_X  [Mc*256];   // [M,256] relu(cat @ Win + b)
__device__ float g_q  [Mc*Ec];    // [B,H,S,HD]
__device__ float g_k  [Mc*Ec];    // [B,H,S,HD]
__device__ float g_v  [Mc*Ec];    // [B,H,S,HD]
__device__ float g_u  [16*Sc];    // u[bh,j] = v[bh,j,:] . Wout[h*32:h*32+32]
__device__ __nv_bfloat16 g_s[(size_t)16*Sc*Sc];  // bf16 scaled scores [bh,i,j] (134MB)

// ---------------- tf32 helpers ----------------
__device__ __forceinline__ uint32_t f2tf(float x) {
    uint32_t r; asm("cvt.rna.tf32.f32 %0, %1;" : "=r"(r) : "f"(x)); return r;
}
__device__ __forceinline__ void mma_tf32(float (&d)[4], const uint32_t (&a)[4],
                                         const uint32_t (&b)[2]) {
    asm volatile("mma.sync.aligned.m16n8k8.row.col.f32.tf32.tf32.f32 "
        "{%0,%1,%2,%3}, {%4,%5,%6,%7}, {%8,%9}, {%0,%1,%2,%3};\n"
        : "+f"(d[0]), "+f"(d[1]), "+f"(d[2]), "+f"(d[3])
        : "r"(a[0]), "r"(a[1]), "r"(a[2]), "r"(a[3]), "r"(b[0]), "r"(b[1]));
}

// ---------------- tf32 MMA GEMM body with fused A-gather (pipelined) ----------------
// BM=128, BN=64, BK=32, 256 threads (8 warps: 4 along M x 2 along N, warp tile 32x32)
// MODE 0: plain A[M,KDIM]
// MODE 1: A = gated concat [itm*y, itm*(1-y), skl*y, skl*(1-y)]  (KDIM=512)
// MODE 2: A = [item_emb[ids], skill_emb[ids]]                     (KDIM=256)
template<int KDIM, int NDIM, int RELU, int HEADOUT, int MODE>
__device__ __forceinline__ void mm_body(const float* __restrict__ A, const float* __restrict__ W,
                                        const float* __restrict__ bias, float* __restrict__ out,
                                        int m0, int n0,
                                        const float* __restrict__ item_emb,
                                        const float* __restrict__ skill_emb,
                                        const int* __restrict__ idxA,
                                        const int* __restrict__ idxB,
                                        const int* __restrict__ lab)
{
    __shared__ uint32_t As[128][36];   // [m][k]
    __shared__ uint32_t Bs[32][72];    // [k][n]
    __shared__ int   sIA[128], sIB[128];
    __shared__ float sY[128];

    int tid = threadIdx.x;
    if (MODE != 0) {
        if (tid < 128) {
            int m = m0 + tid;
            sIA[tid] = idxA[m];
            sIB[tid] = idxB[m];
            if (MODE == 1) sY[tid] = (float)lab[m];
        }
        __syncthreads();
    }

    int w = tid >> 5, lane = tid & 31;
    int g = lane >> 2, tg = lane & 3;
    int wm = w & 3, wn = w >> 2;

    float acc[2][4][4];
    #pragma unroll
    for (int mi = 0; mi < 2; mi++)
        #pragma unroll
        for (int ni = 0; ni < 4; ni++)
            #pragma unroll
            for (int r = 0; r < 4; r++) acc[mi][ni][r] = 0.f;

    float4 av[4]; float4 wv[2];

    auto load_slab = [&](int kt) {
        #pragma unroll
        for (int t = 0; t < 4; t++) {
            int idx = tid + t*256;
            int r = idx >> 3, c = (idx & 7) * 4;
            if (MODE == 0) {
                av[t] = *(const float4*)&A[(size_t)(m0 + r)*KDIM + kt + c];
            } else {
                int k = kt + c;
                int seg = k >> 7, d = k & 127;
                const float* emb = (MODE == 1) ? ((seg < 2) ? item_emb : skill_emb)
                                               : (seg ? skill_emb : item_emb);
                int rowi = (MODE == 1) ? ((seg < 2) ? sIA[r] : sIB[r])
                                       : (seg ? sIB[r] : sIA[r]);
                float4 v = *(const float4*)&emb[(size_t)rowi*Ec + d];
                if (MODE == 1) {
                    float y = sY[r];
                    float gt = (seg & 1) ? (1.f - y) : y;
                    v.x *= gt; v.y *= gt; v.z *= gt; v.w *= gt;
                }
                av[t] = v;
            }
        }
        #pragma unroll
        for (int t = 0; t < 2; t++) {
            int idx = tid + t*256;
            int r = idx >> 4, c = (idx & 15) * 4;
            wv[t] = *(const float4*)&W[(size_t)(kt + r)*NDIM + n0 + c];
        }
    };

    load_slab(0);

    for (int kt = 0; kt < KDIM; kt += 32) {
        __syncthreads();
        #pragma unroll
        for (int t = 0; t < 4; t++) {
            int idx = tid + t*256;
            int r = idx >> 3, c = (idx & 7) * 4;
            uint4 u = { f2tf(av[t].x), f2tf(av[t].y), f2tf(av[t].z), f2tf(av[t].w) };
            *(uint4*)&As[r][c] = u;
        }
        #pragma unroll
        for (int t = 0; t < 2; t++) {
            int idx = tid + t*256;
            int r = idx >> 4, c = (idx & 15) * 4;
            uint4 u = { f2tf(wv[t].x), f2tf(wv[t].y), f2tf(wv[t].z), f2tf(wv[t].w) };
            *(uint4*)&Bs[r][c] = u;
        }
        __syncthreads();

        if (kt + 32 < KDIM) load_slab(kt + 32);   // prefetch hides behind mma below

        #pragma unroll
        for (int kk = 0; kk < 4; kk++) {
            uint32_t a[2][4], b[4][2];
            #pragma unroll
            for (int mi = 0; mi < 2; mi++) {
                int r = wm*32 + mi*16 + g;
                a[mi][0] = As[r][kk*8 + tg];
                a[mi][1] = As[r + 8][kk*8 + tg];
                a[mi][2] = As[r][kk*8 + tg + 4];
                a[mi][3] = As[r + 8][kk*8 + tg + 4];
            }
            #pragma unroll
            for (int ni = 0; ni < 4; ni++) {
                int c = wn*32 + ni*8 + g;
                b[ni][0] = Bs[kk*8 + tg][c];
                b[ni][1] = Bs[kk*8 + tg + 4][c];
            }
            #pragma unroll
            for (int mi = 0; mi < 2; mi++)
                #pragma unroll
                for (int ni = 0; ni < 4; ni++)
                    mma_tf32(acc[mi][ni], a[mi], b[ni]);
        }
    }

    #pragma unroll
    for (int mi = 0; mi < 2; mi++) {
        int rl = m0 + wm*32 + mi*16 + g;
        int rh = rl + 8;
        #pragma unroll
        for (int ni = 0; ni < 4; ni++) {
            int c = n0 + wn*32 + ni*8 + 2*tg;
            float b0 = bias[c], b1 = bias[c+1];
            float v00 = acc[mi][ni][0] + b0, v01 = acc[mi][ni][1] + b1;
            float v10 = acc[mi][ni][2] + b0, v11 = acc[mi][ni][3] + b1;
            if (RELU) {
                v00 = fmaxf(v00, 0.f); v01 = fmaxf(v01, 0.f);
                v10 = fmaxf(v10, 0.f); v11 = fmaxf(v11, 0.f);
            }
            float2 lo = {v00, v01}, hi = {v10, v11};
            if (!HEADOUT) {
                *(float2*)&out[(size_t)rl*NDIM + c] = lo;
                *(float2*)&out[(size_t)rh*NDIM + c] = hi;
            } else {
                int h = c >> 5, d = c & 31;
                *(float2*)&out[(((size_t)((rl >> 11)*Hc + h))*Sc + (rl & 2047))*HDc + d] = lo;
                *(float2*)&out[(((size_t)((rh >> 11)*Hc + h))*Sc + (rh & 2047))*HDc + d] = hi;
            }
        }
    }
}

// X = relu(cat @ Win + b), cat gathered on the fly. grid (4, 64)
__global__ __launch_bounds__(256) void win_kernel(const float* __restrict__ W,
                                                  const float* __restrict__ bias,
                                                  const float* __restrict__ item_emb,
                                                  const float* __restrict__ skill_emb,
                                                  const int* __restrict__ item_in,
                                                  const int* __restrict__ skill_in,
                                                  const int* __restrict__ label_in)
{
    mm_body<512, 256, 1, 0, 1>(nullptr, W, bias, g_X, blockIdx.y*128, blockIdx.x*64,
                               item_emb, skill_emb, item_in, skill_in, label_in);
}

// q/k/v in ONE launch: grid (6, 64); blockIdx.x>>1 selects q/k/v, &1 selects n-half
__global__ __launch_bounds__(256) void qkv_kernel(const float* __restrict__ Wq, const float* __restrict__ bq,
                                                  const float* __restrict__ Wk, const float* __restrict__ bk,
                                                  const float* __restrict__ Wv, const float* __restrict__ bv,
                                                  const float* __restrict__ item_emb,
                                                  const float* __restrict__ skill_emb,
                                                  const int* __restrict__ item_ids,
                                                  const int* __restrict__ skill_ids)
{
    int sel = blockIdx.x >> 1;
    int m0 = blockIdx.y*128, n0 = (blockIdx.x & 1)*64;
    if (sel == 0) {
        mm_body<256, 128, 0, 1, 2>(nullptr, Wq, bq, g_q, m0, n0,
                                   item_emb, skill_emb, item_ids, skill_ids, nullptr);
    } else if (sel == 1) {
        mm_body<256, 128, 0, 1, 0>(g_X, Wk, bk, g_k, m0, n0,
                                   nullptr, nullptr, nullptr, nullptr, nullptr);
    } else {
        mm_body<256, 128, 0, 1, 0>(g_X, Wv, bv, g_v, m0, n0,
                                   nullptr, nullptr, nullptr, nullptr, nullptr);
    }
}

// ---------------- u[bh,j] = v[bh,j,:] . Wout[h*32 : h*32+32] ----------------
__global__ void u_kernel(const float* __restrict__ Wout)
{
    int idx = blockIdx.x*256 + threadIdx.x;   // 0..32767 = bh*Sc + j
    int h = (idx >> 11) & 3;
    const float* vr = g_v + (size_t)idx * HDc;
    const float* wo = Wout + h*32;
    float s = 0.f;
    #pragma unroll
    for (int d4 = 0; d4 < 8; d4++) {
        float4 v4 = *(const float4*)&vr[d4*4];
        float4 w4 = *(const float4*)&wo[d4*4];
        s += v4.x*w4.x + v4.y*w4.y + v4.z*w4.z + v4.w*w4.w;
    }
    g_u[idx] = s;
}

// ---------------- balanced causal QK: one 64x64 tile per block ----------------
// grid (528 tile-pairs, 16 bh), 256 threads. Writes SCALED SCORES as bf16 into g_s.
// No masking needed: combine reads only j<=i entries; masked slots are never read.
// Branch-free, coalesced 128B-row stores via bf16 smem stage.
__global__ __launch_bounds__(256) void qk_kernel()
{
    __shared__ uint32_t Qs[64][36];
    __shared__ uint32_t Ks[64][36];
    __shared__ __nv_bfloat16 Es[64][68];
    int tid = threadIdx.x;
    int t = blockIdx.x, bh = blockIdx.y;

    // decode flattened lower-triangular (it, jt), jt <= it
    int it = (int)((sqrtf(8.f*(float)t + 1.f) - 1.f) * 0.5f);
    while ((it + 1)*(it + 2)/2 <= t) it++;
    while (it*(it + 1)/2 > t) it--;
    int jt = t - it*(it + 1)/2;

    int i0 = it * 64, j0 = jt * 64;
    const float* qp = g_q + (size_t)bh * Sc * HDc;
    const float* kp = g_k + (size_t)bh * Sc * HDc;

    int w = tid >> 5, lane = tid & 31;
    int g = lane >> 2, tg = lane & 3;
    int wm = w & 1, wn = w >> 1;        // warp tile 32(i) x 16(j)

    // load Q (64x32) and K (64x32) tiles
    #pragma unroll
    for (int tt = 0; tt < 2; tt++) {
        int idx = tid + tt*256;
        int r = idx >> 3, c = (idx & 7) * 4;
        float4 v = *(const float4*)&qp[(size_t)(i0 + r)*HDc + c];
        uint4 u = { f2tf(v.x), f2tf(v.y), f2tf(v.z), f2tf(v.w) };
        *(uint4*)&Qs[r][c] = u;
        float4 kv = *(const float4*)&kp[(size_t)(j0 + r)*HDc + c];
        uint4 uk = { f2tf(kv.x), f2tf(kv.y), f2tf(kv.z), f2tf(kv.w) };
        *(uint4*)&Ks[r][c] = uk;
    }
    __syncthreads();

    float acc[2][2][4];
    #pragma unroll
    for (int mi = 0; mi < 2; mi++)
        #pragma unroll
        for (int ni = 0; ni < 2; ni++)
            #pragma unroll
            for (int r = 0; r < 4; r++) acc[mi][ni][r] = 0.f;

    #pragma unroll
    for (int kk = 0; kk < 4; kk++) {
        uint32_t a[2][4], b[2][2];
        #pragma unroll
        for (int mi = 0; mi < 2; mi++) {
            int r = wm*32 + mi*16 + g;
            a[mi][0] = Qs[r][kk*8 + tg];
            a[mi][1] = Qs[r + 8][kk*8 + tg];
            a[mi][2] = Qs[r][kk*8 + tg + 4];
            a[mi][3] = Qs[r + 8][kk*8 + tg + 4];
        }
        #pragma unroll
        for (int ni = 0; ni < 2; ni++) {
            int c = wn*16 + ni*8 + g;
            b[ni][0] = Ks[c][kk*8 + tg];
            b[ni][1] = Ks[c][kk*8 + tg + 4];
        }
        #pragma unroll
        for (int mi = 0; mi < 2; mi++)
            #pragma unroll
            for (int ni = 0; ni < 2; ni++)
                mma_tf32(acc[mi][ni], a[mi], b[ni]);
    }

    const float scale = 0.17677669529663687f;   // 1/sqrt(32)

    // stage bf16 scaled scores in smem
    #pragma unroll
    for (int mi = 0; mi < 2; mi++) {
        int r = wm*32 + mi*16 + g;
        #pragma unroll
        for (int ni = 0; ni < 2; ni++) {
            int cl = wn*16 + ni*8 + 2*tg;
            *(__nv_bfloat162*)&Es[r][cl] =
                __floats2bfloat162_rn(acc[mi][ni][0]*scale, acc[mi][ni][1]*scale);
            *(__nv_bfloat162*)&Es[r + 8][cl] =
                __floats2bfloat162_rn(acc[mi][ni][2]*scale, acc[mi][ni][3]*scale);
        }
    }
    __syncthreads();

    // coalesced write: per row 16 threads x 8B = 128B contiguous
    __nv_bfloat16* sbase = g_s + (size_t)bh * SSs;
    int sr = tid >> 4, sc4 = (tid & 15) * 4;
    #pragma unroll
    for (int tt = 0; tt < 4; tt++) {
        int row = sr + tt*16;
        uint2 v = *(uint2*)&Es[row][sc4];
        *(uint2*)&sbase[(size_t)(i0 + row)*Sc + j0 + sc4] = v;
    }
}

// ---------------- combine: exp(bf16 scores) + Zp + softmax blend + normalize + PRED ----------------
// One block per row (b, i). Reads bf16 causal scores, computes exp into Pr smem,
// reduces Zp, rescales, writes final prob, accumulates pred on the fly.
__global__ __launch_bounds__(256) void combine_kernel(const float* __restrict__ rel,
        const float* __restrict__ ts, const float* __restrict__ l1p,
        const float* __restrict__ l2p, const float* __restrict__ bout,
        float* __restrict__ prob, float* __restrict__ pred)
{
    __shared__ float Pr[4][Sc];      // exp of causal scores (32KB)
    __shared__ float E[Sc];          // exp of ts/rel (8KB)
    __shared__ float sred[6][8];
    __shared__ float spred[8];
    int bi = blockIdx.x;             // row id = b*S + i
    int b = bi >> 11, i = bi & 2047;
    int tid = threadIdx.x;
    const float* tsr = ts  + (size_t)bi * Sc;
    const float* rlr = rel + (size_t)bi * Sc;
    size_t base0 = (size_t)(b*Hc)*SSs + (size_t)i*Sc;
    const __nv_bfloat16* s0 = g_s + (size_t)(b*Hc)*SSs + (size_t)i*Sc;

    float zt = 0.f, zr = 0.f;
    float zp[4] = {0.f, 0.f, 0.f, 0.f};

    #pragma unroll
    for (int t = 0; t < 2; t++) {
        int j = tid*4 + t*1024;
        if (j + 3 <= i) {
            float4 tv = *(const float4*)&tsr[j];
            float v0 = __expf(__expf(-fabsf(tv.x)));
            float v1 = __expf(__expf(-fabsf(tv.y)));
            float v2 = __expf(__expf(-fabsf(tv.z)));
            float v3 = __expf(__expf(-fabsf(tv.w)));
            *(float4*)&E[j] = make_float4(v0, v1, v2, v3);
            zt += (v0+v1) + (v2+v3);
            #pragma unroll
            for (int h = 0; h < 4; h++) {
                uint2 sv = *(const uint2*)(s0 + (size_t)h*SSs + j);
                __nv_bfloat162 s01 = *(__nv_bfloat162*)&sv.x;
                __nv_bfloat162 s23 = *(__nv_bfloat162*)&sv.y;
                float e0 = __expf(__low2float(s01));
                float e1 = __expf(__high2float(s01));
                float e2 = __expf(__low2float(s23));
                float e3 = __expf(__high2float(s23));
                *(float4*)&Pr[h][j] = make_float4(e0, e1, e2, e3);
                zp[h] += (e0 + e1) + (e2 + e3);
            }
        } else if (j > i) {
            float4 rv = *(const float4*)&rlr[j];
            float v0 = (rv.x == 0.f) ? 0.f : __expf(rv.x);
            float v1 = (rv.y == 0.f) ? 0.f : __expf(rv.y);
            float v2 = (rv.z == 0.f) ? 0.f : __expf(rv.z);
            float v3 = (rv.w == 0.f) ? 0.f : __expf(rv.w);
            *(float4*)&E[j] = make_float4(v0, v1, v2, v3);
            zr += (v0+v1) + (v2+v3);
        } else {
            #pragma unroll
            for (int u = 0; u < 4; u++) {
                int jj = j + u;
                if (jj <= i) {
                    float v = __expf(__expf(-fabsf(tsr[jj])));
                    E[jj] = v; zt += v;
                    #pragma unroll
                    for (int h = 0; h < 4; h++) {
                        float p = __expf(__bfloat162float(s0[(size_t)h*SSs + jj]));
                        Pr[h][jj] = p; zp[h] += p;
                    }
                } else {
                    float rv = rlr[jj];
                    float v = (rv == 0.f) ? 0.f : __expf(rv);
                    E[jj] = v; zr += v;
                }
            }
        }
    }
    #pragma unroll
    for (int o = 16; o; o >>= 1) {
        zt += __shfl_xor_sync(0xffffffffu, zt, o);
        zr += __shfl_xor_sync(0xffffffffu, zr, o);
        #pragma unroll
        for (int h = 0; h < 4; h++) zp[h] += __shfl_xor_sync(0xffffffffu, zp[h], o);
    }
    if ((tid & 31) == 0) {
        int wi = tid >> 5;
        sred[0][wi] = zt; sred[1][wi] = zr;
        #pragma unroll
        for (int h = 0; h < 4; h++) sred[2 + h][wi] = zp[h];
    }
    __syncthreads();
    zt = 0.f; zr = 0.f; zp[0] = zp[1] = zp[2] = zp[3] = 0.f;
    #pragma unroll
    for (int wi = 0; wi < 8; wi++) {
        zt += sred[0][wi]; zr += sred[1][wi];
        #pragma unroll
        for (int h = 0; h < 4; h++) zp[h] += sred[2 + h][wi];
    }

    float l1 = *l1p, l2 = *l2p;
    float ct = (1.f - l1) * l2 / zt;
    float cr = 0.f, uni = 0.f;
    if (i == Sc - 1) uni = l1 / (float)Sc;   // all rel logits masked -> uniform softmax
    else             cr  = l1 / zr;
    float cp[4];
    #pragma unroll
    for (int h = 0; h < 4; h++)
        cp[h] = (1.f - l1) * (1.f - l2) / zp[h];

    float pacc = 0.f;
    #pragma unroll
    for (int t = 0; t < 2; t++) {
        int j = tid*4 + t*1024;
        float4 u4[4];
        #pragma unroll
        for (int h = 0; h < 4; h++)
            u4[h] = *(const float4*)&g_u[(size_t)((b*Hc + h)*Sc) + j];
        if (j + 3 <= i) {
            float4 e4 = *(float4*)&E[j];
            float a0 = ct*e4.x + uni, a1 = ct*e4.y + uni;
            float a2 = ct*e4.z + uni, a3 = ct*e4.w + uni;
            #pragma unroll
            for (int h = 0; h < 4; h++) {
                float4 p = *(float4*)&Pr[h][j];
                p.x = cp[h]*p.x + a0; p.y = cp[h]*p.y + a1;
                p.z = cp[h]*p.z + a2; p.w = cp[h]*p.w + a3;
                *(float4*)&prob[base0 + (size_t)h*SSs + j] = p;
                pacc += p.x*u4[h].x + p.y*u4[h].y + p.z*u4[h].z + p.w*u4[h].w;
            }
        } else if (j > i) {
            float4 e4 = *(float4*)&E[j];
            float4 v = { cr*e4.x, cr*e4.y, cr*e4.z, cr*e4.w };
            float4 us = { u4[0].x + u4[1].x + u4[2].x + u4[3].x,
                          u4[0].y + u4[1].y + u4[2].y + u4[3].y,
                          u4[0].z + u4[1].z + u4[2].z + u4[3].z,
                          u4[0].w + u4[1].w + u4[2].w + u4[3].w };
            #pragma unroll
            for (int h = 0; h < 4; h++)
                *(float4*)&prob[base0 + (size_t)h*SSs + j] = v;
            pacc += v.x*us.x + v.y*us.y + v.z*us.z + v.w*us.w;
        } else {
            #pragma unroll
            for (int u = 0; u < 4; u++) {
                int jj = j + u;
                float uu[4] = { ((float*)&u4[0])[u], ((float*)&u4[1])[u],
                                ((float*)&u4[2])[u], ((float*)&u4[3])[u] };
                if (jj <= i) {
                    float add = ct*E[jj] + uni;
                    #pragma unroll
                    for (int h = 0; h < 4; h++) {
                        float p = cp[h]*Pr[h][jj] + add;
                        prob[base0 + (size_t)h*SSs + jj] = p;
                        pacc += p * uu[h];
                    }
                } else {
                    float v = cr*E[jj];
                    #pragma unroll
                    for (int h = 0; h < 4; h++) {
                        prob[base0 + (size_t)h*SSs + jj] = v;
                        pacc += v * uu[h];
                    }
                }
            }
        }
    }

    // reduce pred across block
    #pragma unroll
    for (int o = 16; o; o >>= 1) pacc += __shfl_xor_sync(0xffffffffu, pacc, o);
    if ((tid & 31) == 0) spred[tid >> 5] = pacc;
    __syncthreads();
    if (tid == 0) {
        float s = 0.f;
        #pragma unroll
        for (int wi = 0; wi < 8; wi++) s += spred[wi];
        pred[bi] = s + bout[0];
    }
}

// ---------------- launch ----------------
extern "C" void kernel_launch(void* const* d_in, const int* in_sizes, int n_in,
                              void* d_out, int out_size)
{
    (void)in_sizes; (void)n_in; (void)out_size;
    const int*   item_inputs  = (const int*)  d_in[0];
    const int*   skill_inputs = (const int*)  d_in[1];
    const int*   label_inputs = (const int*)  d_in[2];
    const int*   item_ids     = (const int*)  d_in[3];
    const int*   skill_ids    = (const int*)  d_in[4];
    const float* rel          = (const float*)d_in[5];
    const float* ts           = (const float*)d_in[6];
    const float* item_emb     = (const float*)d_in[7];
    const float* skill_emb    = (const float*)d_in[8];
    const float* Win          = (const float*)d_in[9];
    const float* b_in         = (const float*)d_in[10];
    const float* Wq           = (const float*)d_in[11];
    const float* bq           = (const float*)d_in[12];
    const float* Wk           = (const float*)d_in[13];
    const float* bk           = (const float*)d_in[14];
    const float* Wv           = (const float*)d_in[15];
    const float* bv           = (const float*)d_in[16];
    const float* Wout         = (const float*)d_in[17];
    const float* bout         = (const float*)d_in[18];
    const float* l1           = (const float*)d_in[19];
    const float* l2           = (const float*)d_in[20];

    float* pred = (float*)d_out;
    float* prob = pred + Mc;          // pred [8192] then prob_attn [B,H,S,S]

    win_kernel<<<dim3(4, 64), 256>>>(Win, b_in, item_emb, skill_emb,
                                     item_inputs, skill_inputs, label_inputs);
    qkv_kernel<<<dim3(6, 64), 256>>>(Wq, bq, Wk, bk, Wv, bv,
                                     item_emb, skill_emb, item_ids, skill_ids);
    u_kernel<<<128, 256>>>(Wout);
    qk_kernel<<<dim3(528, 16), 256>>>();
    combine_kernel<<<Mc, 256>>>(rel, ts, l1, l2, bout, prob, pred);
}

// round 14
// speedup vs baseline: 1.6318x; 1.0235x over previous
#include <cuda_runtime.h>
#include <cuda_bf16.h>
#include <math.h>
#include <stdint.h>

#define Bc 4
#define Sc 2048
#define Ec 128
#define Hc 4
#define HDc 32
#define Mc (Bc*Sc)            // 8192 tokens
#define SSs ((size_t)Sc*(size_t)Sc)

// ---------------- scratch (device globals: allocation-free) ----------------
__device__ float g_X  [Mc*256];   // [M,256] relu(cat @ Win + b)
__device__ float g_q  [Mc*Ec];    // [B,H,S,HD]
__device__ float g_k  [Mc*Ec];    // [B,H,S,HD]
__device__ float g_v  [Mc*Ec];    // [B,H,S,HD]
__device__ float g_u  [16*Sc];    // u[bh,j] = v[bh,j,:] . Wout[h*32:h*32+32]
__device__ __nv_bfloat16 g_s[(size_t)16*Sc*Sc];  // bf16 scaled scores [bh,i,j] (134MB)

// ---------------- tf32 helpers ----------------
__device__ __forceinline__ uint32_t f2tf(float x) {
    uint32_t r; asm("cvt.rna.tf32.f32 %0, %1;" : "=r"(r) : "f"(x)); return r;
}
__device__ __forceinline__ void mma_tf32(float (&d)[4], const uint32_t (&a)[4],
                                         const uint32_t (&b)[2]) {
    asm volatile("mma.sync.aligned.m16n8k8.row.col.f32.tf32.tf32.f32 "
        "{%0,%1,%2,%3}, {%4,%5,%6,%7}, {%8,%9}, {%0,%1,%2,%3};\n"
        : "+f"(d[0]), "+f"(d[1]), "+f"(d[2]), "+f"(d[3])
        : "r"(a[0]), "r"(a[1]), "r"(a[2]), "r"(a[3]), "r"(b[0]), "r"(b[1]));
}

// ---------------- tf32 MMA GEMM body with fused A-gather (pipelined) ----------------
// BM=128, BN=64, BK=32, 256 threads (8 warps: 4 along M x 2 along N, warp tile 32x32)
// MODE 0: plain A[M,KDIM]
// MODE 1: A = gated concat [itm*y, itm*(1-y), skl*y, skl*(1-y)]  (KDIM=512)
// MODE 2: A = [item_emb[ids], skill_emb[ids]]                     (KDIM=256)
template<int KDIM, int NDIM, int RELU, int HEADOUT, int MODE>
__device__ __forceinline__ void mm_body(const float* __restrict__ A, const float* __restrict__ W,
                                        const float* __restrict__ bias, float* __restrict__ out,
                                        int m0, int n0,
                                        const float* __restrict__ item_emb,
                                        const float* __restrict__ skill_emb,
                                        const int* __restrict__ idxA,
                                        const int* __restrict__ idxB,
                                        const int* __restrict__ lab)
{
    __shared__ uint32_t As[128][36];   // [m][k]
    __shared__ uint32_t Bs[32][72];    // [k][n]
    __shared__ int   sIA[128], sIB[128];
    __shared__ float sY[128];

    int tid = threadIdx.x;
    if (MODE != 0) {
        if (tid < 128) {
            int m = m0 + tid;
            sIA[tid] = idxA[m];
            sIB[tid] = idxB[m];
            if (MODE == 1) sY[tid] = (float)lab[m];
        }
        __syncthreads();
    }

    int w = tid >> 5, lane = tid & 31;
    int g = lane >> 2, tg = lane & 3;
    int wm = w & 3, wn = w >> 2;

    float acc[2][4][4];
    #pragma unroll
    for (int mi = 0; mi < 2; mi++)
        #pragma unroll
        for (int ni = 0; ni < 4; ni++)
            #pragma unroll
            for (int r = 0; r < 4; r++) acc[mi][ni][r] = 0.f;

    float4 av[4]; float4 wv[2];

    auto load_slab = [&](int kt) {
        #pragma unroll
        for (int t = 0; t < 4; t++) {
            int idx = tid + t*256;
            int r = idx >> 3, c = (idx & 7) * 4;
            if (MODE == 0) {
                av[t] = *(const float4*)&A[(size_t)(m0 + r)*KDIM + kt + c];
            } else {
                int k = kt + c;
                int seg = k >> 7, d = k & 127;
                const float* emb = (MODE == 1) ? ((seg < 2) ? item_emb : skill_emb)
                                               : (seg ? skill_emb : item_emb);
                int rowi = (MODE == 1) ? ((seg < 2) ? sIA[r] : sIB[r])
                                       : (seg ? sIB[r] : sIA[r]);
                float4 v = *(const float4*)&emb[(size_t)rowi*Ec + d];
                if (MODE == 1) {
                    float y = sY[r];
                    float gt = (seg & 1) ? (1.f - y) : y;
                    v.x *= gt; v.y *= gt; v.z *= gt; v.w *= gt;
                }
                av[t] = v;
            }
        }
        #pragma unroll
        for (int t = 0; t < 2; t++) {
            int idx = tid + t*256;
            int r = idx >> 4, c = (idx & 15) * 4;
            wv[t] = *(const float4*)&W[(size_t)(kt + r)*NDIM + n0 + c];
        }
    };

    load_slab(0);

    for (int kt = 0; kt < KDIM; kt += 32) {
        __syncthreads();
        #pragma unroll
        for (int t = 0; t < 4; t++) {
            int idx = tid + t*256;
            int r = idx >> 3, c = (idx & 7) * 4;
            uint4 u = { f2tf(av[t].x), f2tf(av[t].y), f2tf(av[t].z), f2tf(av[t].w) };
            *(uint4*)&As[r][c] = u;
        }
        #pragma unroll
        for (int t = 0; t < 2; t++) {
            int idx = tid + t*256;
            int r = idx >> 4, c = (idx & 15) * 4;
            uint4 u = { f2tf(wv[t].x), f2tf(wv[t].y), f2tf(wv[t].z), f2tf(wv[t].w) };
            *(uint4*)&Bs[r][c] = u;
        }
        __syncthreads();

        if (kt + 32 < KDIM) load_slab(kt + 32);   // prefetch hides behind mma below

        #pragma unroll
        for (int kk = 0; kk < 4; kk++) {
            uint32_t a[2][4], b[4][2];
            #pragma unroll
            for (int mi = 0; mi < 2; mi++) {
                int r = wm*32 + mi*16 + g;
                a[mi][0] = As[r][kk*8 + tg];
                a[mi][1] = As[r + 8][kk*8 + tg];
                a[mi][2] = As[r][kk*8 + tg + 4];
                a[mi][3] = As[r + 8][kk*8 + tg + 4];
            }
            #pragma unroll
            for (int ni = 0; ni < 4; ni++) {
                int c = wn*32 + ni*8 + g;
                b[ni][0] = Bs[kk*8 + tg][c];
                b[ni][1] = Bs[kk*8 + tg + 4][c];
            }
            #pragma unroll
            for (int mi = 0; mi < 2; mi++)
                #pragma unroll
                for (int ni = 0; ni < 4; ni++)
                    mma_tf32(acc[mi][ni], a[mi], b[ni]);
        }
    }

    #pragma unroll
    for (int mi = 0; mi < 2; mi++) {
        int rl = m0 + wm*32 + mi*16 + g;
        int rh = rl + 8;
        #pragma unroll
        for (int ni = 0; ni < 4; ni++) {
            int c = n0 + wn*32 + ni*8 + 2*tg;
            float b0 = bias[c], b1 = bias[c+1];
            float v00 = acc[mi][ni][0] + b0, v01 = acc[mi][ni][1] + b1;
            float v10 = acc[mi][ni][2] + b0, v11 = acc[mi][ni][3] + b1;
            if (RELU) {
                v00 = fmaxf(v00, 0.f); v01 = fmaxf(v01, 0.f);
                v10 = fmaxf(v10, 0.f); v11 = fmaxf(v11, 0.f);
            }
            float2 lo = {v00, v01}, hi = {v10, v11};
            if (!HEADOUT) {
                *(float2*)&out[(size_t)rl*NDIM + c] = lo;
                *(float2*)&out[(size_t)rh*NDIM + c] = hi;
            } else {
                int h = c >> 5, d = c & 31;
                *(float2*)&out[(((size_t)((rl >> 11)*Hc + h))*Sc + (rl & 2047))*HDc + d] = lo;
                *(float2*)&out[(((size_t)((rh >> 11)*Hc + h))*Sc + (rh & 2047))*HDc + d] = hi;
            }
        }
    }
}

// X = relu(cat @ Win + b), cat gathered on the fly. grid (4, 64)
__global__ __launch_bounds__(256) void win_kernel(const float* __restrict__ W,
                                                  const float* __restrict__ bias,
                                                  const float* __restrict__ item_emb,
                                                  const float* __restrict__ skill_emb,
                                                  const int* __restrict__ item_in,
                                                  const int* __restrict__ skill_in,
                                                  const int* __restrict__ label_in)
{
    mm_body<512, 256, 1, 0, 1>(nullptr, W, bias, g_X, blockIdx.y*128, blockIdx.x*64,
                               item_emb, skill_emb, item_in, skill_in, label_in);
}

// q/k/v in ONE launch: grid (6, 64); blockIdx.x>>1 selects q/k/v, &1 selects n-half
__global__ __launch_bounds__(256) void qkv_kernel(const float* __restrict__ Wq, const float* __restrict__ bq,
                                                  const float* __restrict__ Wk, const float* __restrict__ bk,
                                                  const float* __restrict__ Wv, const float* __restrict__ bv,
                                                  const float* __restrict__ item_emb,
                                                  const float* __restrict__ skill_emb,
                                                  const int* __restrict__ item_ids,
                                                  const int* __restrict__ skill_ids)
{
    int sel = blockIdx.x >> 1;
    int m0 = blockIdx.y*128, n0 = (blockIdx.x & 1)*64;
    if (sel == 0) {
        mm_body<256, 128, 0, 1, 2>(nullptr, Wq, bq, g_q, m0, n0,
                                   item_emb, skill_emb, item_ids, skill_ids, nullptr);
    } else if (sel == 1) {
        mm_body<256, 128, 0, 1, 0>(g_X, Wk, bk, g_k, m0, n0,
                                   nullptr, nullptr, nullptr, nullptr, nullptr);
    } else {
        mm_body<256, 128, 0, 1, 0>(g_X, Wv, bv, g_v, m0, n0,
                                   nullptr, nullptr, nullptr, nullptr, nullptr);
    }
}

// ---------------- u[bh,j] = v[bh,j,:] . Wout[h*32 : h*32+32] ----------------
__global__ void u_kernel(const float* __restrict__ Wout)
{
    int idx = blockIdx.x*256 + threadIdx.x;   // 0..32767 = bh*Sc + j
    int h = (idx >> 11) & 3;
    const float* vr = g_v + (size_t)idx * HDc;
    const float* wo = Wout + h*32;
    float s = 0.f;
    #pragma unroll
    for (int d4 = 0; d4 < 8; d4++) {
        float4 v4 = *(const float4*)&vr[d4*4];
        float4 w4 = *(const float4*)&wo[d4*4];
        s += v4.x*w4.x + v4.y*w4.y + v4.z*w4.z + v4.w*w4.w;
    }
    g_u[idx] = s;
}

// ---------------- balanced causal QK: 128(i) x 64(j) tile per block ----------------
// grid (272 tile-pairs, 16 bh), 256 threads (8 warps: 4 along i x 2 along j, warp 32x32).
// Writes SCALED SCORES as bf16 into g_s. No masking: combine reads only j<=i entries.
__global__ __launch_bounds__(256) void qk_kernel()
{
    __shared__ uint32_t Qs[128][36];
    __shared__ uint32_t Ks[64][36];
    __shared__ __nv_bfloat16 Es[128][68];
    int tid = threadIdx.x;
    int t = blockIdx.x, bh = blockIdx.y;

    // decode (it, jt): it in 0..15 (128-row i-tiles), jt in 0..2*it+1 (64-col j-tiles)
    // cumulative before it = it*(it+1)
    int it = (int)((sqrtf(4.f*(float)t + 1.f) - 1.f) * 0.5f);
    while ((it + 1)*(it + 2) <= t) it++;
    while (it*(it + 1) > t) it--;
    int jt = t - it*(it + 1);

    int i0 = it * 128, j0 = jt * 64;
    const float* qp = g_q + (size_t)bh * Sc * HDc;
    const float* kp = g_k + (size_t)bh * Sc * HDc;

    int w = tid >> 5, lane = tid & 31;
    int g = lane >> 2, tg = lane & 3;
    int wm = w & 3, wn = w >> 2;        // warp tile 32(i) x 32(j)

    // load Q (128x32) and K (64x32) tiles
    #pragma unroll
    for (int tt = 0; tt < 4; tt++) {
        int idx = tid + tt*256;
        int r = idx >> 3, c = (idx & 7) * 4;
        float4 v = *(const float4*)&qp[(size_t)(i0 + r)*HDc + c];
        uint4 u = { f2tf(v.x), f2tf(v.y), f2tf(v.z), f2tf(v.w) };
        *(uint4*)&Qs[r][c] = u;
    }
    #pragma unroll
    for (int tt = 0; tt < 2; tt++) {
        int idx = tid + tt*256;
        int r = idx >> 3, c = (idx & 7) * 4;
        float4 kv = *(const float4*)&kp[(size_t)(j0 + r)*HDc + c];
        uint4 uk = { f2tf(kv.x), f2tf(kv.y), f2tf(kv.z), f2tf(kv.w) };
        *(uint4*)&Ks[r][c] = uk;
    }
    __syncthreads();

    float acc[2][4][4];
    #pragma unroll
    for (int mi = 0; mi < 2; mi++)
        #pragma unroll
        for (int ni = 0; ni < 4; ni++)
            #pragma unroll
            for (int r = 0; r < 4; r++) acc[mi][ni][r] = 0.f;

    #pragma unroll
    for (int kk = 0; kk < 4; kk++) {
        uint32_t a[2][4], b[4][2];
        #pragma unroll
        for (int mi = 0; mi < 2; mi++) {
            int r = wm*32 + mi*16 + g;
            a[mi][0] = Qs[r][kk*8 + tg];
            a[mi][1] = Qs[r + 8][kk*8 + tg];
            a[mi][2] = Qs[r][kk*8 + tg + 4];
            a[mi][3] = Qs[r + 8][kk*8 + tg + 4];
        }
        #pragma unroll
        for (int ni = 0; ni < 4; ni++) {
            int c = wn*32 + ni*8 + g;      // j index acts as "n"
            b[ni][0] = Ks[c][kk*8 + tg];
            b[ni][1] = Ks[c][kk*8 + tg + 4];
        }
        #pragma unroll
        for (int mi = 0; mi < 2; mi++)
            #pragma unroll
            for (int ni = 0; ni < 4; ni++)
                mma_tf32(acc[mi][ni], a[mi], b[ni]);
    }

    const float scale = 0.17677669529663687f;   // 1/sqrt(32)

    // stage bf16 scaled scores in smem
    #pragma unroll
    for (int mi = 0; mi < 2; mi++) {
        int r = wm*32 + mi*16 + g;
        #pragma unroll
        for (int ni = 0; ni < 4; ni++) {
            int cl = wn*32 + ni*8 + 2*tg;
            *(__nv_bfloat162*)&Es[r][cl] =
                __floats2bfloat162_rn(acc[mi][ni][0]*scale, acc[mi][ni][1]*scale);
            *(__nv_bfloat162*)&Es[r + 8][cl] =
                __floats2bfloat162_rn(acc[mi][ni][2]*scale, acc[mi][ni][3]*scale);
        }
    }
    __syncthreads();

    // coalesced write: per row 16 threads x 8B = 128B contiguous
    __nv_bfloat16* sbase = g_s + (size_t)bh * SSs;
    int sr = tid >> 4, sc4 = (tid & 15) * 4;
    #pragma unroll
    for (int tt = 0; tt < 8; tt++) {
        int row = sr + tt*16;
        uint2 v = *(uint2*)&Es[row][sc4];
        *(uint2*)&sbase[(size_t)(i0 + row)*Sc + j0 + sc4] = v;
    }
}

// ---------------- combine: exp(bf16 scores) + Zp + softmax blend + normalize + PRED ----------------
// One block per row (b, i). Reads bf16 causal scores, computes exp into Pr smem,
// reduces Zp, rescales, writes final prob, accumulates pred on the fly.
__global__ __launch_bounds__(256) void combine_kernel(const float* __restrict__ rel,
        const float* __restrict__ ts, const float* __restrict__ l1p,
        const float* __restrict__ l2p, const float* __restrict__ bout,
        float* __restrict__ prob, float* __restrict__ pred)
{
    __shared__ float Pr[4][Sc];      // exp of causal scores (32KB)
    __shared__ float E[Sc];          // exp of ts/rel (8KB)
    __shared__ float sred[6][8];
    __shared__ float spred[8];
    int bi = blockIdx.x;             // row id = b*S + i
    int b = bi >> 11, i = bi & 2047;
    int tid = threadIdx.x;
    const float* tsr = ts  + (size_t)bi * Sc;
    const float* rlr = rel + (size_t)bi * Sc;
    size_t base0 = (size_t)(b*Hc)*SSs + (size_t)i*Sc;
    const __nv_bfloat16* s0 = g_s + (size_t)(b*Hc)*SSs + (size_t)i*Sc;

    float zt = 0.f, zr = 0.f;
    float zp[4] = {0.f, 0.f, 0.f, 0.f};

    #pragma unroll
    for (int t = 0; t < 2; t++) {
        int j = tid*4 + t*1024;
        if (j + 3 <= i) {
            float4 tv = *(const float4*)&tsr[j];
            float v0 = __expf(__expf(-fabsf(tv.x)));
            float v1 = __expf(__expf(-fabsf(tv.y)));
            float v2 = __expf(__expf(-fabsf(tv.z)));
            float v3 = __expf(__expf(-fabsf(tv.w)));
            *(float4*)&E[j] = make_float4(v0, v1, v2, v3);
            zt += (v0+v1) + (v2+v3);
            #pragma unroll
            for (int h = 0; h < 4; h++) {
                uint2 sv = *(const uint2*)(s0 + (size_t)h*SSs + j);
                __nv_bfloat162 s01 = *(__nv_bfloat162*)&sv.x;
                __nv_bfloat162 s23 = *(__nv_bfloat162*)&sv.y;
                float e0 = __expf(__low2float(s01));
                float e1 = __expf(__high2float(s01));
                float e2 = __expf(__low2float(s23));
                float e3 = __expf(__high2float(s23));
                *(float4*)&Pr[h][j] = make_float4(e0, e1, e2, e3);
                zp[h] += (e0 + e1) + (e2 + e3);
            }
        } else if (j > i) {
            float4 rv = *(const float4*)&rlr[j];
            float v0 = (rv.x == 0.f) ? 0.f : __expf(rv.x);
            float v1 = (rv.y == 0.f) ? 0.f : __expf(rv.y);
            float v2 = (rv.z == 0.f) ? 0.f : __expf(rv.z);
            float v3 = (rv.w == 0.f) ? 0.f : __expf(rv.w);
            *(float4*)&E[j] = make_float4(v0, v1, v2, v3);
            zr += (v0+v1) + (v2+v3);
        } else {
            #pragma unroll
            for (int u = 0; u < 4; u++) {
                int jj = j + u;
                if (jj <= i) {
                    float v = __expf(__expf(-fabsf(tsr[jj])));
                    E[jj] = v; zt += v;
                    #pragma unroll
                    for (int h = 0; h < 4; h++) {
                        float p = __expf(__bfloat162float(s0[(size_t)h*SSs + jj]));
                        Pr[h][jj] = p; zp[h] += p;
                    }
                } else {
                    float rv = rlr[jj];
                    float v = (rv == 0.f) ? 0.f : __expf(rv);
                    E[jj] = v; zr += v;
                }
            }
        }
    }
    #pragma unroll
    for (int o = 16; o; o >>= 1) {
        zt += __shfl_xor_sync(0xffffffffu, zt, o);
        zr += __shfl_xor_sync(0xffffffffu, zr, o);
        #pragma unroll
        for (int h = 0; h < 4; h++) zp[h] += __shfl_xor_sync(0xffffffffu, zp[h], o);
    }
    if ((tid & 31) == 0) {
        int wi = tid >> 5;
        sred[0][wi] = zt; sred[1][wi] = zr;
        #pragma unroll
        for (int h = 0; h < 4; h++) sred[2 + h][wi] = zp[h];
    }
    __syncthreads();
    zt = 0.f; zr = 0.f; zp[0] = zp[1] = zp[2] = zp[3] = 0.f;
    #pragma unroll
    for (int wi = 0; wi < 8; wi++) {
        zt += sred[0][wi]; zr += sred[1][wi];
        #pragma unroll
        for (int h = 0; h < 4; h++) zp[h] += sred[2 + h][wi];
    }

    float l1 = *l1p, l2 = *l2p;
    float ct = (1.f - l1) * l2 / zt;
    float cr = 0.f, uni = 0.f;
    if (i == Sc - 1) uni = l1 / (float)Sc;   // all rel logits masked -> uniform softmax
    else             cr  = l1 / zr;
    float cp[4];
    #pragma unroll
    for (int h = 0; h < 4; h++)
        cp[h] = (1.f - l1) * (1.f - l2) / zp[h];

    float pacc = 0.f;
    #pragma unroll
    for (int t = 0; t < 2; t++) {
        int j = tid*4 + t*1024;
        float4 u4[4];
        #pragma unroll
        for (int h = 0; h < 4; h++)
            u4[h] = *(const float4*)&g_u[(size_t)((b*Hc + h)*Sc) + j];
        if (j + 3 <= i) {
            float4 e4 = *(float4*)&E[j];
            float a0 = ct*e4.x + uni, a1 = ct*e4.y + uni;
            float a2 = ct*e4.z + uni, a3 = ct*e4.w + uni;
            #pragma unroll
            for (int h = 0; h < 4; h++) {
                float4 p = *(float4*)&Pr[h][j];
                p.x = cp[h]*p.x + a0; p.y = cp[h]*p.y + a1;
                p.z = cp[h]*p.z + a2; p.w = cp[h]*p.w + a3;
                *(float4*)&prob[base0 + (size_t)h*SSs + j] = p;
                pacc += p.x*u4[h].x + p.y*u4[h].y + p.z*u4[h].z + p.w*u4[h].w;
            }
        } else if (j > i) {
            float4 e4 = *(float4*)&E[j];
            float4 v = { cr*e4.x, cr*e4.y, cr*e4.z, cr*e4.w };
            float4 us = { u4[0].x + u4[1].x + u4[2].x + u4[3].x,
                          u4[0].y + u4[1].y + u4[2].y + u4[3].y,
                          u4[0].z + u4[1].z + u4[2].z + u4[3].z,
                          u4[0].w + u4[1].w + u4[2].w + u4[3].w };
            #pragma unroll
            for (int h = 0; h < 4; h++)
                *(float4*)&prob[base0 + (size_t)h*SSs + j] = v;
            pacc += v.x*us.x + v.y*us.y + v.z*us.z + v.w*us.w;
        } else {
            #pragma unroll
            for (int u = 0; u < 4; u++) {
                int jj = j + u;
                float uu[4] = { ((float*)&u4[0])[u], ((float*)&u4[1])[u],
                                ((float*)&u4[2])[u], ((float*)&u4[3])[u] };
                if (jj <= i) {
                    float add = ct*E[jj] + uni;
                    #pragma unroll
                    for (int h = 0; h < 4; h++) {
                        float p = cp[h]*Pr[h][jj] + add;
                        prob[base0 + (size_t)h*SSs + jj] = p;
                        pacc += p * uu[h];
                    }
                } else {
                    float v = cr*E[jj];
                    #pragma unroll
                    for (int h = 0; h < 4; h++) {
                        prob[base0 + (size_t)h*SSs + jj] = v;
                        pacc += v * uu[h];
                    }
                }
            }
        }
    }

    // reduce pred across block
    #pragma unroll
    for (int o = 16; o; o >>= 1) pacc += __shfl_xor_sync(0xffffffffu, pacc, o);
    if ((tid & 31) == 0) spred[tid >> 5] = pacc;
    __syncthreads();
    if (tid == 0) {
        float s = 0.f;
        #pragma unroll
        for (int wi = 0; wi < 8; wi++) s += spred[wi];
        pred[bi] = s + bout[0];
    }
}

// ---------------- launch ----------------
extern "C" void kernel_launch(void* const* d_in, const int* in_sizes, int n_in,
                              void* d_out, int out_size)
{
    (void)in_sizes; (void)n_in; (void)out_size;
    const int*   item_inputs  = (const int*)  d_in[0];
    const int*   skill_inputs = (const int*)  d_in[1];
    const int*   label_inputs = (const int*)  d_in[2];
    const int*   item_ids     = (const int*)  d_in[3];
    const int*   skill_ids    = (const int*)  d_in[4];
    const float* rel          = (const float*)d_in[5];
    const float* ts           = (const float*)d_in[6];
    const float* item_emb     = (const float*)d_in[7];
    const float* skill_emb    = (const float*)d_in[8];
    const float* Win          = (const float*)d_in[9];
    const float* b_in         = (const float*)d_in[10];
    const float* Wq           = (const float*)d_in[11];
    const float* bq           = (const float*)d_in[12];
    const float* Wk           = (const float*)d_in[13];
    const float* bk           = (const float*)d_in[14];
    const float* Wv           = (const float*)d_in[15];
    const float* bv           = (const float*)d_in[16];
    const float* Wout         = (const float*)d_in[17];
    const float* bout         = (const float*)d_in[18];
    const float* l1           = (const float*)d_in[19];
    const float* l2           = (const float*)d_in[20];

    float* pred = (float*)d_out;
    float* prob = pred + Mc;          // pred [8192] then prob_attn [B,H,S,S]

    win_kernel<<<dim3(4, 64), 256>>>(Win, b_in, item_emb, skill_emb,
                                     item_inputs, skill_inputs, label_inputs);
    qkv_kernel<<<dim3(6, 64), 256>>>(Wq, bq, Wk, bk, Wv, bv,
                                     item_emb, skill_emb, item_ids, skill_ids);
    u_kernel<<<128, 256>>>(Wout);
    qk_kernel<<<dim3(272, 16), 256>>>();
    combine_kernel<<<Mc, 256>>>(rel, ts, l1, l2, bout, prob, pred);
}